// round 1
// baseline (speedup 1.0000x reference)
#include <cuda_runtime.h>
#include <math.h>

// Problem constants
#define Bb 16
#define Ee 512
#define Tt 512
#define Hh 1024
#define Rr 32
#define Pp 8192
#define Ww 3
#define KCONV (Ee*Ww)   // 1536

// Scratch (device globals: allocation-free per harness rules)
__device__ float g_x1[Bb*Ee*Tt];     // after conv block 1, layout (B,E,T)
__device__ float g_xbte[Bb*Tt*Ee];   // after conv block 2, layout (B,T,E)
__device__ float g_maxed[Pp*Ee];     // span-max head+tail, (P,E)
__device__ float g_h1[Pp*Hh];
__device__ float g_h2[Pp*Hh];

// ---------------------------------------------------------------------------
// Residual conv block as implicit-im2col SGEMM.
//   y[b][eo][t] = relu( sum_{ei,k} w[eo][ei][k] * x[b][ei][t+k-1] + bias[eo] ) + x[b][eo][t]
// A = w viewed as (E, E*W) row-major (kk = ei*3+k). B = im2col of x, built on the fly.
// MODE 0: read param x (B,E,T), write g_x1 (B,E,T)
// MODE 1: read g_x1,          write g_xbte (B,T,E)  [transposed for gather]
// Tile: 128(M=eo) x 128(N=b*t) x 8, 256 threads, 8x8 per thread.
// ---------------------------------------------------------------------------
template<int MODE>
__global__ __launch_bounds__(256) void conv_block_kernel(
    const float* __restrict__ xin_param,
    const float* __restrict__ w,
    const float* __restrict__ bias)
{
    const float* __restrict__ xin = (MODE == 0) ? xin_param : (const float*)g_x1;
    float* __restrict__ out       = (MODE == 0) ? (float*)g_x1 : (float*)g_xbte;

    __shared__ float As[8][128];
    __shared__ float Bs[8][128];

    const int tid = threadIdx.x;
    const int n0 = blockIdx.x * 128;   // column tile over (b,t); T=512 -> tile stays in one b
    const int m0 = blockIdx.y * 128;   // row tile over eo
    const int tx = tid & 15;
    const int ty = tid >> 4;

    float acc[8][8];
    #pragma unroll
    for (int i = 0; i < 8; i++)
        #pragma unroll
        for (int j = 0; j < 8; j++) acc[i][j] = 0.f;

    // B-load coords: thread covers column bj, rows {bi0, bi0+2, bi0+4, bi0+6}
    const int bj  = tid & 127;
    const int bi0 = tid >> 7;          // 0 or 1
    const int ncol = n0 + bj;
    const int bb = ncol >> 9;          // / T
    const int tcol = ncol & 511;       // % T
    const float* __restrict__ xb = xin + (size_t)bb * (Ee * Tt);

    // A-load coords: thread loads float4 at row ar, k-seg as
    const int ar = tid >> 1;
    const int as = (tid & 1) * 4;

    for (int k0 = 0; k0 < KCONV; k0 += 8) {
        // A tile (conv weights, always in-bounds: 512 x 1536)
        float4 a4 = *(const float4*)&w[(size_t)(m0 + ar) * KCONV + k0 + as];
        As[as + 0][ar] = a4.x;
        As[as + 1][ar] = a4.y;
        As[as + 2][ar] = a4.z;
        As[as + 3][ar] = a4.w;

        // B tile: im2col with zero padding at t edges
        #pragma unroll
        for (int r = 0; r < 4; r++) {
            int i  = bi0 + r * 2;
            int kk = k0 + i;
            int ei = kk / 3;
            int dk = kk - ei * 3;       // 0..2
            int st = tcol + dk - 1;
            float v = 0.f;
            if (st >= 0 && st < Tt) v = xb[(size_t)ei * Tt + st];
            Bs[i][bj] = v;
        }
        __syncthreads();

        #pragma unroll
        for (int k = 0; k < 8; k++) {
            float4 a0 = *(const float4*)&As[k][ty * 4];
            float4 a1 = *(const float4*)&As[k][ty * 4 + 64];
            float4 b0 = *(const float4*)&Bs[k][tx * 4];
            float4 b1 = *(const float4*)&Bs[k][tx * 4 + 64];
            float av[8] = {a0.x, a0.y, a0.z, a0.w, a1.x, a1.y, a1.z, a1.w};
            float bv[8] = {b0.x, b0.y, b0.z, b0.w, b1.x, b1.y, b1.z, b1.w};
            #pragma unroll
            for (int ii = 0; ii < 8; ii++)
                #pragma unroll
                for (int jj = 0; jj < 8; jj++)
                    acc[ii][jj] += av[ii] * bv[jj];
        }
        __syncthreads();
    }

    // Epilogue: bias + relu + residual, write per MODE layout
    #pragma unroll
    for (int ii = 0; ii < 8; ii++) {
        int m = m0 + ty * 4 + ((ii < 4) ? ii : (64 + ii - 4));
        float bvv = bias[m];
        #pragma unroll
        for (int jj = 0; jj < 8; jj++) {
            int nn = n0 + tx * 4 + ((jj < 4) ? jj : (64 + jj - 4));
            int b2 = nn >> 9;
            int t2 = nn & 511;
            float res = xin[((size_t)b2 * Ee + m) * Tt + t2];
            float v = acc[ii][jj] + bvv;
            v = (v > 0.f ? v : 0.f) + res;
            if (MODE == 0) out[((size_t)b2 * Ee + m) * Tt + t2] = v;
            else           out[((size_t)b2 * Tt + t2) * Ee + m] = v;
        }
    }
}

// ---------------------------------------------------------------------------
// Span max gather: maxed[p][:] = max over head span + max over tail span
// Reads g_xbte (B,T,E) coalesced along E via float4.
// ---------------------------------------------------------------------------
__global__ __launch_bounds__(128) void span_kernel(
    const int* __restrict__ bidx,
    const int* __restrict__ hidx, const int* __restrict__ hspan,
    const int* __restrict__ tidx, const int* __restrict__ tspan)
{
    const int p  = blockIdx.x;
    const int e4 = threadIdx.x;                 // float4 index over E/4 = 128
    const int b  = bidx[p];
    const float4* __restrict__ base = (const float4*)g_xbte + (size_t)b * Tt * (Ee / 4);

    const int h0 = hidx[p], hs = hspan[p];
    const int t0 = tidx[p], ts = tspan[p];

    float4 hm = make_float4(-INFINITY, -INFINITY, -INFINITY, -INFINITY);
    for (int s = 0; s < hs; s++) {
        float4 v = base[(size_t)(h0 + s) * (Ee / 4) + e4];
        hm.x = fmaxf(hm.x, v.x); hm.y = fmaxf(hm.y, v.y);
        hm.z = fmaxf(hm.z, v.z); hm.w = fmaxf(hm.w, v.w);
    }
    float4 tm = make_float4(-INFINITY, -INFINITY, -INFINITY, -INFINITY);
    for (int s = 0; s < ts; s++) {
        float4 v = base[(size_t)(t0 + s) * (Ee / 4) + e4];
        tm.x = fmaxf(tm.x, v.x); tm.y = fmaxf(tm.y, v.y);
        tm.z = fmaxf(tm.z, v.z); tm.w = fmaxf(tm.w, v.w);
    }
    float4 o = make_float4(hm.x + tm.x, hm.y + tm.y, hm.z + tm.z, hm.w + tm.w);
    ((float4*)g_maxed)[(size_t)p * (Ee / 4) + e4] = o;
}

// ---------------------------------------------------------------------------
// NT SGEMM: C[m][n] = act( sum_k A[m][k] * Bm[n][k] + bias[n] )
// A (M,K) row-major, Bm (N,K) row-major, C (M,N) row-major.
// 128x128x8 tile, 256 threads, 8x8 per thread. M%128==0, K%8==0 assumed;
// N bounds-checked (handles N=32 for the final layer).
// ---------------------------------------------------------------------------
template<bool RELU>
__global__ __launch_bounds__(256) void gemm_nt_kernel(
    const float* __restrict__ A,
    const float* __restrict__ Bm,
    const float* __restrict__ bias,
    float* __restrict__ C,
    int M, int N, int K)
{
    __shared__ float As[8][128];
    __shared__ float Bs[8][128];

    const int tid = threadIdx.x;
    const int n0 = blockIdx.x * 128;
    const int m0 = blockIdx.y * 128;
    const int tx = tid & 15;
    const int ty = tid >> 4;

    float acc[8][8];
    #pragma unroll
    for (int i = 0; i < 8; i++)
        #pragma unroll
        for (int j = 0; j < 8; j++) acc[i][j] = 0.f;

    const int r = tid >> 1;
    const int s = (tid & 1) * 4;
    const bool bvalid = (n0 + r) < N;

    for (int k0 = 0; k0 < K; k0 += 8) {
        float4 a4 = *(const float4*)&A[(size_t)(m0 + r) * K + k0 + s];
        As[s + 0][r] = a4.x; As[s + 1][r] = a4.y;
        As[s + 2][r] = a4.z; As[s + 3][r] = a4.w;

        float4 b4 = make_float4(0.f, 0.f, 0.f, 0.f);
        if (bvalid) b4 = *(const float4*)&Bm[(size_t)(n0 + r) * K + k0 + s];
        Bs[s + 0][r] = b4.x; Bs[s + 1][r] = b4.y;
        Bs[s + 2][r] = b4.z; Bs[s + 3][r] = b4.w;
        __syncthreads();

        #pragma unroll
        for (int k = 0; k < 8; k++) {
            float4 a0 = *(const float4*)&As[k][ty * 4];
            float4 a1 = *(const float4*)&As[k][ty * 4 + 64];
            float4 b0 = *(const float4*)&Bs[k][tx * 4];
            float4 b1 = *(const float4*)&Bs[k][tx * 4 + 64];
            float av[8] = {a0.x, a0.y, a0.z, a0.w, a1.x, a1.y, a1.z, a1.w};
            float bv[8] = {b0.x, b0.y, b0.z, b0.w, b1.x, b1.y, b1.z, b1.w};
            #pragma unroll
            for (int ii = 0; ii < 8; ii++)
                #pragma unroll
                for (int jj = 0; jj < 8; jj++)
                    acc[ii][jj] += av[ii] * bv[jj];
        }
        __syncthreads();
    }

    #pragma unroll
    for (int ii = 0; ii < 8; ii++) {
        int m = m0 + ty * 4 + ((ii < 4) ? ii : (64 + ii - 4));
        #pragma unroll
        for (int jj = 0; jj < 8; jj++) {
            int nn = n0 + tx * 4 + ((jj < 4) ? jj : (64 + jj - 4));
            if (nn < N) {
                float v = acc[ii][jj] + bias[nn];
                if (RELU) v = (v > 0.f) ? v : 0.f;
                C[(size_t)m * N + nn] = v;
            }
        }
    }
}

// ---------------------------------------------------------------------------
// Pack the remaining outputs: trig_attn (passthrough) and rel_labels (as float)
// ---------------------------------------------------------------------------
__global__ void pack_kernel(const float* __restrict__ trig,
                            const int* __restrict__ labels,
                            float* __restrict__ out, int out_size)
{
    int i = blockIdx.x * blockDim.x + threadIdx.x;
    const int PR = Pp * Rr;
    const int BT = Bb * Tt;
    if (out_size >= PR + BT && i < BT)        out[PR + i]      = trig[i];
    if (out_size >= PR + BT + Pp && i < Pp)   out[PR + BT + i] = (float)labels[i];
}

// ---------------------------------------------------------------------------
extern "C" void kernel_launch(void* const* d_in, const int* in_sizes, int n_in,
                              void* d_out, int out_size)
{
    const float* x     = (const float*)d_in[0];   // rel_word_x (B,E,T)
    const float* trig  = (const float*)d_in[1];   // trig_attn (B,T)
    const int*   bidx  = (const int*)  d_in[2];
    const int*   hidx  = (const int*)  d_in[3];
    const int*   hspan = (const int*)  d_in[4];
    const int*   tidx  = (const int*)  d_in[5];
    const int*   tspan = (const int*)  d_in[6];
    const int*   labels= (const int*)  d_in[7];
    const float* c1w   = (const float*)d_in[8];
    const float* c1b   = (const float*)d_in[9];
    const float* c2w   = (const float*)d_in[10];
    const float* c2b   = (const float*)d_in[11];
    const float* w1    = (const float*)d_in[12];
    const float* b1    = (const float*)d_in[13];
    const float* w2    = (const float*)d_in[14];
    const float* b2    = (const float*)d_in[15];
    const float* wr    = (const float*)d_in[16];
    const float* br    = (const float*)d_in[17];
    float* out = (float*)d_out;

    float *pmaxed, *ph1, *ph2;
    cudaGetSymbolAddress((void**)&pmaxed, g_maxed);
    cudaGetSymbolAddress((void**)&ph1,    g_h1);
    cudaGetSymbolAddress((void**)&ph2,    g_h2);

    // Conv block 1: (B,E,T) -> g_x1 (B,E,T)
    {
        dim3 grid((Bb * Tt) / 128, Ee / 128);   // 64 x 4
        conv_block_kernel<0><<<grid, 256>>>(x, c1w, c1b);
    }
    // Conv block 2: g_x1 -> g_xbte (B,T,E), transposed for gather
    {
        dim3 grid((Bb * Tt) / 128, Ee / 128);
        conv_block_kernel<1><<<grid, 256>>>(nullptr, c2w, c2b);
    }
    // Span max gather
    span_kernel<<<Pp, 128>>>(bidx, hidx, hspan, tidx, tspan);

    // FC1: (P,512) x (1024,512)^T -> (P,1024), relu
    {
        dim3 grid(Hh / 128, Pp / 128);          // 8 x 64
        gemm_nt_kernel<true><<<grid, 256>>>(pmaxed, w1, b1, ph1, Pp, Hh, Ee);
    }
    // FC2: (P,1024) x (1024,1024)^T -> (P,1024), relu
    {
        dim3 grid(Hh / 128, Pp / 128);
        gemm_nt_kernel<true><<<grid, 256>>>(ph1, w2, b2, ph2, Pp, Hh, Hh);
    }
    // FC3: (P,1024) x (32,1024)^T -> (P,32), no act, straight into d_out
    {
        dim3 grid(1, Pp / 128);
        gemm_nt_kernel<false><<<grid, 256>>>(ph2, wr, br, out, Pp, Rr, Hh);
    }
    // trig_attn + rel_labels passthrough
    pack_kernel<<<(8192 + 255) / 256, 256>>>(trig, labels, out, out_size);
}

// round 2
// speedup vs baseline: 1.1821x; 1.1821x over previous
#include <cuda_runtime.h>
#include <math.h>

// Problem constants
#define Bb 16
#define Ee 512
#define Tt 512
#define Hh 1024
#define Rr 32
#define Pp 8192
#define Ww 3
#define KCONV (Ee*Ww)   // 1536

// Scratch (device globals: allocation-free per harness rules)
__device__ float g_x1[Bb*Ee*Tt];     // after conv block 1, layout (B,E,T)
__device__ float g_xbte[Bb*Tt*Ee];   // after conv block 2, layout (B,T,E)
__device__ float g_maxed[Pp*Ee];     // span-max head+tail, (P,E)
__device__ float g_h1[Pp*Hh];
__device__ float g_h2[Pp*Hh];

// ---------------------------------------------------------------------------
// Residual conv block as implicit-im2col SGEMM with double-buffered smem.
//   y[b][eo][t] = relu( conv(x)[b][eo][t] + bias[eo] ) + x[b][eo][t]
// MODE 0: read param x (B,E,T), write g_x1 (B,E,T)
// MODE 1: read g_x1,          write g_xbte (B,T,E)  [transposed for gather]
// Tile: 128(M=eo) x 128(N=b*t) x 8, 256 threads, 8x8 per thread.
// ---------------------------------------------------------------------------
template<int MODE>
__global__ __launch_bounds__(256, 2) void conv_block_kernel(
    const float* __restrict__ xin_param,
    const float* __restrict__ w,
    const float* __restrict__ bias)
{
    const float* __restrict__ xin = (MODE == 0) ? xin_param : (const float*)g_x1;
    float* __restrict__ out       = (MODE == 0) ? (float*)g_x1 : (float*)g_xbte;

    __shared__ float As[2][8][128];
    __shared__ float Bs[2][8][128];

    const int tid = threadIdx.x;
    const int n0 = blockIdx.x * 128;   // column tile over (b,t)
    const int m0 = blockIdx.y * 128;   // row tile over eo
    const int tx = tid & 15;
    const int ty = tid >> 4;

    float acc[8][8];
    #pragma unroll
    for (int i = 0; i < 8; i++)
        #pragma unroll
        for (int j = 0; j < 8; j++) acc[i][j] = 0.f;

    // B-load coords: thread covers column bj, rows {bi0, bi0+2, bi0+4, bi0+6}
    const int bj  = tid & 127;
    const int bi0 = tid >> 7;          // 0 or 1
    const int ncol = n0 + bj;
    const int bb = ncol >> 9;          // / T
    const int tcol = ncol & 511;       // % T
    const float* __restrict__ xb = xin + (size_t)bb * (Ee * Tt);

    // A-load coords: thread loads float4 at row ar, k-seg as
    const int ar = tid >> 1;
    const int as = (tid & 1) * 4;
    const float* __restrict__ wrow = w + (size_t)(m0 + ar) * KCONV + as;

    // prefetch regs
    float4 a_n;
    float  b_n[4];

    // ---- load tile k0=0 ----
    a_n = *(const float4*)&wrow[0];
    #pragma unroll
    for (int r = 0; r < 4; r++) {
        int i  = bi0 + r * 2;
        int kk = i;                    // k0 = 0
        int ei = kk / 3;
        int dk = kk - ei * 3;
        int st = tcol + dk - 1;
        b_n[r] = (st >= 0 && st < Tt) ? xb[(size_t)ei * Tt + st] : 0.f;
    }
    As[0][as + 0][ar] = a_n.x; As[0][as + 1][ar] = a_n.y;
    As[0][as + 2][ar] = a_n.z; As[0][as + 3][ar] = a_n.w;
    #pragma unroll
    for (int r = 0; r < 4; r++) Bs[0][bi0 + r * 2][bj] = b_n[r];
    __syncthreads();

    int buf = 0;
    for (int k0 = 8; k0 <= KCONV; k0 += 8) {
        const bool more = (k0 < KCONV);
        if (more) {
            a_n = *(const float4*)&wrow[k0];
            #pragma unroll
            for (int r = 0; r < 4; r++) {
                int i  = bi0 + r * 2;
                int kk = k0 + i;
                int ei = kk / 3;
                int dk = kk - ei * 3;
                int st = tcol + dk - 1;
                b_n[r] = (st >= 0 && st < Tt) ? xb[(size_t)ei * Tt + st] : 0.f;
            }
        }

        #pragma unroll
        for (int k = 0; k < 8; k++) {
            float4 a0 = *(const float4*)&As[buf][k][ty * 4];
            float4 a1 = *(const float4*)&As[buf][k][ty * 4 + 64];
            float4 b0 = *(const float4*)&Bs[buf][k][tx * 4];
            float4 b1 = *(const float4*)&Bs[buf][k][tx * 4 + 64];
            float av[8] = {a0.x, a0.y, a0.z, a0.w, a1.x, a1.y, a1.z, a1.w};
            float bv[8] = {b0.x, b0.y, b0.z, b0.w, b1.x, b1.y, b1.z, b1.w};
            #pragma unroll
            for (int ii = 0; ii < 8; ii++)
                #pragma unroll
                for (int jj = 0; jj < 8; jj++)
                    acc[ii][jj] += av[ii] * bv[jj];
        }

        if (more) {
            int nb = buf ^ 1;
            As[nb][as + 0][ar] = a_n.x; As[nb][as + 1][ar] = a_n.y;
            As[nb][as + 2][ar] = a_n.z; As[nb][as + 3][ar] = a_n.w;
            #pragma unroll
            for (int r = 0; r < 4; r++) Bs[nb][bi0 + r * 2][bj] = b_n[r];
            buf = nb;
            __syncthreads();
        }
    }

    // Epilogue: bias + relu + residual, write per MODE layout
    #pragma unroll
    for (int ii = 0; ii < 8; ii++) {
        int m = m0 + ty * 4 + ((ii < 4) ? ii : (64 + ii - 4));
        float bvv = bias[m];
        #pragma unroll
        for (int jj = 0; jj < 8; jj++) {
            int nn = n0 + tx * 4 + ((jj < 4) ? jj : (64 + jj - 4));
            int b2 = nn >> 9;
            int t2 = nn & 511;
            float res = xin[((size_t)b2 * Ee + m) * Tt + t2];
            float v = acc[ii][jj] + bvv;
            v = (v > 0.f ? v : 0.f) + res;
            if (MODE == 0) out[((size_t)b2 * Ee + m) * Tt + t2] = v;
            else           out[((size_t)b2 * Tt + t2) * Ee + m] = v;
        }
    }
}

// ---------------------------------------------------------------------------
// Span max gather: maxed[p][:] = max over head span + max over tail span
// ---------------------------------------------------------------------------
__global__ __launch_bounds__(128) void span_kernel(
    const int* __restrict__ bidx,
    const int* __restrict__ hidx, const int* __restrict__ hspan,
    const int* __restrict__ tidx, const int* __restrict__ tspan)
{
    const int p  = blockIdx.x;
    const int e4 = threadIdx.x;                 // float4 index over E/4 = 128
    const int b  = bidx[p];
    const float4* __restrict__ base = (const float4*)g_xbte + (size_t)b * Tt * (Ee / 4);

    const int h0 = hidx[p], hs = hspan[p];
    const int t0 = tidx[p], ts = tspan[p];

    float4 hm = make_float4(-INFINITY, -INFINITY, -INFINITY, -INFINITY);
    for (int s = 0; s < hs; s++) {
        float4 v = base[(size_t)(h0 + s) * (Ee / 4) + e4];
        hm.x = fmaxf(hm.x, v.x); hm.y = fmaxf(hm.y, v.y);
        hm.z = fmaxf(hm.z, v.z); hm.w = fmaxf(hm.w, v.w);
    }
    float4 tm = make_float4(-INFINITY, -INFINITY, -INFINITY, -INFINITY);
    for (int s = 0; s < ts; s++) {
        float4 v = base[(size_t)(t0 + s) * (Ee / 4) + e4];
        tm.x = fmaxf(tm.x, v.x); tm.y = fmaxf(tm.y, v.y);
        tm.z = fmaxf(tm.z, v.z); tm.w = fmaxf(tm.w, v.w);
    }
    float4 o = make_float4(hm.x + tm.x, hm.y + tm.y, hm.z + tm.z, hm.w + tm.w);
    ((float4*)g_maxed)[(size_t)p * (Ee / 4) + e4] = o;
}

// ---------------------------------------------------------------------------
// NT SGEMM with double-buffered smem:
//   C[m][n] = act( sum_k A[m][k] * Bm[n][k] + bias[n] )
// 128x128x8 tile, 256 threads, 8x8 per thread. N bounds-checked.
// ---------------------------------------------------------------------------
template<bool RELU>
__global__ __launch_bounds__(256, 2) void gemm_nt_kernel(
    const float* __restrict__ A,
    const float* __restrict__ Bm,
    const float* __restrict__ bias,
    float* __restrict__ C,
    int M, int N, int K)
{
    __shared__ float As[2][8][128];
    __shared__ float Bs[2][8][128];

    const int tid = threadIdx.x;
    const int n0 = blockIdx.x * 128;
    const int m0 = blockIdx.y * 128;
    const int tx = tid & 15;
    const int ty = tid >> 4;

    float acc[8][8];
    #pragma unroll
    for (int i = 0; i < 8; i++)
        #pragma unroll
        for (int j = 0; j < 8; j++) acc[i][j] = 0.f;

    const int r = tid >> 1;
    const int s = (tid & 1) * 4;
    const bool bvalid = (n0 + r) < N;
    const float* __restrict__ Arow = A  + (size_t)(m0 + r) * K + s;
    const float* __restrict__ Brow = Bm + (size_t)(n0 + r) * K + s;

    float4 a_n, b_n;

    // ---- load tile k0=0 ----
    a_n = *(const float4*)&Arow[0];
    b_n = bvalid ? *(const float4*)&Brow[0] : make_float4(0.f, 0.f, 0.f, 0.f);
    As[0][s + 0][r] = a_n.x; As[0][s + 1][r] = a_n.y;
    As[0][s + 2][r] = a_n.z; As[0][s + 3][r] = a_n.w;
    Bs[0][s + 0][r] = b_n.x; Bs[0][s + 1][r] = b_n.y;
    Bs[0][s + 2][r] = b_n.z; Bs[0][s + 3][r] = b_n.w;
    __syncthreads();

    int buf = 0;
    for (int k0 = 8; k0 <= K; k0 += 8) {
        const bool more = (k0 < K);
        if (more) {
            a_n = *(const float4*)&Arow[k0];
            b_n = bvalid ? *(const float4*)&Brow[k0] : make_float4(0.f, 0.f, 0.f, 0.f);
        }

        #pragma unroll
        for (int k = 0; k < 8; k++) {
            float4 a0 = *(const float4*)&As[buf][k][ty * 4];
            float4 a1 = *(const float4*)&As[buf][k][ty * 4 + 64];
            float4 b0 = *(const float4*)&Bs[buf][k][tx * 4];
            float4 b1 = *(const float4*)&Bs[buf][k][tx * 4 + 64];
            float av[8] = {a0.x, a0.y, a0.z, a0.w, a1.x, a1.y, a1.z, a1.w};
            float bv[8] = {b0.x, b0.y, b0.z, b0.w, b1.x, b1.y, b1.z, b1.w};
            #pragma unroll
            for (int ii = 0; ii < 8; ii++)
                #pragma unroll
                for (int jj = 0; jj < 8; jj++)
                    acc[ii][jj] += av[ii] * bv[jj];
        }

        if (more) {
            int nb = buf ^ 1;
            As[nb][s + 0][r] = a_n.x; As[nb][s + 1][r] = a_n.y;
            As[nb][s + 2][r] = a_n.z; As[nb][s + 3][r] = a_n.w;
            Bs[nb][s + 0][r] = b_n.x; Bs[nb][s + 1][r] = b_n.y;
            Bs[nb][s + 2][r] = b_n.z; Bs[nb][s + 3][r] = b_n.w;
            buf = nb;
            __syncthreads();
        }
    }

    #pragma unroll
    for (int ii = 0; ii < 8; ii++) {
        int m = m0 + ty * 4 + ((ii < 4) ? ii : (64 + ii - 4));
        #pragma unroll
        for (int jj = 0; jj < 8; jj++) {
            int nn = n0 + tx * 4 + ((jj < 4) ? jj : (64 + jj - 4));
            if (nn < N) {
                float v = acc[ii][jj] + bias[nn];
                if (RELU) v = (v > 0.f) ? v : 0.f;
                C[(size_t)m * N + nn] = v;
            }
        }
    }
}

// ---------------------------------------------------------------------------
// Pack the remaining outputs: trig_attn (passthrough) and rel_labels (as float)
// ---------------------------------------------------------------------------
__global__ void pack_kernel(const float* __restrict__ trig,
                            const int* __restrict__ labels,
                            float* __restrict__ out, int out_size)
{
    int i = blockIdx.x * blockDim.x + threadIdx.x;
    const int PR = Pp * Rr;
    const int BT = Bb * Tt;
    if (out_size >= PR + BT && i < BT)        out[PR + i]      = trig[i];
    if (out_size >= PR + BT + Pp && i < Pp)   out[PR + BT + i] = (float)labels[i];
}

// ---------------------------------------------------------------------------
extern "C" void kernel_launch(void* const* d_in, const int* in_sizes, int n_in,
                              void* d_out, int out_size)
{
    const float* x     = (const float*)d_in[0];
    const float* trig  = (const float*)d_in[1];
    const int*   bidx  = (const int*)  d_in[2];
    const int*   hidx  = (const int*)  d_in[3];
    const int*   hspan = (const int*)  d_in[4];
    const int*   tidx  = (const int*)  d_in[5];
    const int*   tspan = (const int*)  d_in[6];
    const int*   labels= (const int*)  d_in[7];
    const float* c1w   = (const float*)d_in[8];
    const float* c1b   = (const float*)d_in[9];
    const float* c2w   = (const float*)d_in[10];
    const float* c2b   = (const float*)d_in[11];
    const float* w1    = (const float*)d_in[12];
    const float* b1    = (const float*)d_in[13];
    const float* w2    = (const float*)d_in[14];
    const float* b2    = (const float*)d_in[15];
    const float* wr    = (const float*)d_in[16];
    const float* br    = (const float*)d_in[17];
    float* out = (float*)d_out;

    float *pmaxed, *ph1, *ph2;
    cudaGetSymbolAddress((void**)&pmaxed, g_maxed);
    cudaGetSymbolAddress((void**)&ph1,    g_h1);
    cudaGetSymbolAddress((void**)&ph2,    g_h2);

    // Conv block 1: (B,E,T) -> g_x1 (B,E,T)
    {
        dim3 grid((Bb * Tt) / 128, Ee / 128);   // 64 x 4
        conv_block_kernel<0><<<grid, 256>>>(x, c1w, c1b);
    }
    // Conv block 2: g_x1 -> g_xbte (B,T,E)
    {
        dim3 grid((Bb * Tt) / 128, Ee / 128);
        conv_block_kernel<1><<<grid, 256>>>(nullptr, c2w, c2b);
    }
    // Span max gather
    span_kernel<<<Pp, 128>>>(bidx, hidx, hspan, tidx, tspan);

    // FC1: (P,512) x (1024,512)^T -> (P,1024), relu
    {
        dim3 grid(Hh / 128, Pp / 128);
        gemm_nt_kernel<true><<<grid, 256>>>(pmaxed, w1, b1, ph1, Pp, Hh, Ee);
    }
    // FC2: (P,1024) x (1024,1024)^T -> (P,1024), relu
    {
        dim3 grid(Hh / 128, Pp / 128);
        gemm_nt_kernel<true><<<grid, 256>>>(ph1, w2, b2, ph2, Pp, Hh, Hh);
    }
    // FC3: (P,1024) x (32,1024)^T -> (P,32), no act, straight into d_out
    {
        dim3 grid(1, Pp / 128);
        gemm_nt_kernel<false><<<grid, 256>>>(ph2, wr, br, out, Pp, Rr, Hh);
    }
    // trig_attn + rel_labels passthrough
    pack_kernel<<<(8192 + 255) / 256, 256>>>(trig, labels, out, out_size);
}

// round 3
// speedup vs baseline: 1.1981x; 1.0135x over previous
#include <cuda_runtime.h>
#include <math.h>

// Problem constants
#define Bb 16
#define Ee 512
#define Tt 512
#define Hh 1024
#define Rr 32
#define Pp 8192
#define Ww 3
#define KCONV (Ee*Ww)   // 1536

// Scratch (device globals: allocation-free per harness rules)
__device__ float g_x1[Bb*Ee*Tt];     // after conv block 1, layout (B,E,T)
__device__ float g_xbte[Bb*Tt*Ee];   // after conv block 2, layout (B,T,E)
__device__ float g_maxed[Pp*Ee];     // span-max head+tail, (P,E)
__device__ float g_h1[Pp*Hh];
__device__ float g_h2[Pp*Hh];

// ---------------------------------------------------------------------------
// Residual conv block as halo-tile 3-tap GEMM, double-buffered.
//   y[b][eo][t] = relu( sum_{ei,dk} w[eo][ei][dk] * x[b][ei][t+dk-1] + bias[eo] ) + x[b][eo][t]
// K-loop over ei in slabs of 8. Per slab:
//   Xs[k][i]  : x[b][ei0+k][t0-1 .. t0+128]   (i = t_local + 4, width 136)
//   Ws[f][m]  : w[m0+m][(ei0+k)*3+dk], f = k*3+dk  (flat, no div in hot path)
// Tile: 128(M=eo) x 128(N=t within one b) x 8(ei), 256 threads, 8x8 per thread,
// 3 taps accumulated per (ii,jj) -> 192 FFMA / 12 LDS per k-step.
// MODE 0: read param x (B,E,T), write g_x1 (B,E,T)
// MODE 1: read g_x1,           write g_xbte (B,T,E)
// ---------------------------------------------------------------------------
template<int MODE>
__global__ __launch_bounds__(256, 2) void conv_block_kernel(
    const float* __restrict__ xin_param,
    const float* __restrict__ w,
    const float* __restrict__ bias)
{
    const float* __restrict__ xin = (MODE == 0) ? xin_param : (const float*)g_x1;
    float* __restrict__ out       = (MODE == 0) ? (float*)g_x1 : (float*)g_xbte;

    __shared__ float Xs[2][8][136];     // [buf][k][t_local+4], valid i in [3,132]
    __shared__ float Ws[2][24*128];     // [buf][(k*3+dk)*128 + m]

    const int tid = threadIdx.x;
    const int n0 = blockIdx.x * 128;    // (b, t-tile); T=512 -> tile within one b
    const int m0 = blockIdx.y * 128;    // eo tile
    const int b  = n0 >> 9;
    const int t0 = n0 & 511;
    const int tx = tid & 15;
    const int ty = tid >> 4;

    float acc[8][8];
    #pragma unroll
    for (int i = 0; i < 8; i++)
        #pragma unroll
        for (int j = 0; j < 8; j++) acc[i][j] = 0.f;

    // --- X load mapping: warp xrow loads row xrow (one ei), 32 lanes * float4
    const int xrow = tid >> 5;          // 0..7
    const int lane = tid & 31;
    const bool lval = (t0 > 0);             // left halo in-bounds
    const bool rval = (t0 + 128 < Tt);      // right halo in-bounds
    const float* __restrict__ xrow_base0 = xin + ((size_t)b * Ee + xrow) * Tt + t0;

    // --- W load mapping: 768 float4 per slab, 3 per thread
    int wm[3], wq4[3];
    #pragma unroll
    for (int j = 0; j < 3; j++) {
        int f4idx = tid + 256 * j;
        wm[j]  = f4idx / 6;             // eo row within tile (0..127)
        wq4[j] = (f4idx % 6) * 4;       // float offset within 24-float slab row
    }
    const float* __restrict__ wbase0 = w + (size_t)m0 * KCONV;

    // prefetch registers
    float4 xr; float xh0 = 0.f, xh1 = 0.f;
    float4 wr4[3];

    // ---- prefetch + store slab 0 ----
    {
        const float* xr0 = xrow_base0;                 // ei0 = 0
        xr = *(const float4*)&xr0[lane * 4];
        if (lane == 0) xh0 = lval ? xr0[-1]  : 0.f;
        if (lane == 1) xh1 = rval ? xr0[128] : 0.f;
        #pragma unroll
        for (int j = 0; j < 3; j++)
            wr4[j] = *(const float4*)&wbase0[(size_t)wm[j] * KCONV + wq4[j]];

        Xs[0][xrow][4 + lane * 4 + 0] = xr.x;
        Xs[0][xrow][4 + lane * 4 + 1] = xr.y;
        Xs[0][xrow][4 + lane * 4 + 2] = xr.z;
        Xs[0][xrow][4 + lane * 4 + 3] = xr.w;
        if (lane == 0) Xs[0][xrow][3]   = xh0;
        if (lane == 1) Xs[0][xrow][132] = xh1;
        #pragma unroll
        for (int j = 0; j < 3; j++) {
            Ws[0][(wq4[j] + 0) * 128 + wm[j]] = wr4[j].x;
            Ws[0][(wq4[j] + 1) * 128 + wm[j]] = wr4[j].y;
            Ws[0][(wq4[j] + 2) * 128 + wm[j]] = wr4[j].z;
            Ws[0][(wq4[j] + 3) * 128 + wm[j]] = wr4[j].w;
        }
    }
    __syncthreads();

    int buf = 0;
    for (int ei0 = 8; ei0 <= Ee; ei0 += 8) {
        const bool more = (ei0 < Ee);
        if (more) {
            const float* xr0 = xrow_base0 + (size_t)ei0 * Tt;
            xr = *(const float4*)&xr0[lane * 4];
            if (lane == 0) xh0 = lval ? xr0[-1]  : 0.f;
            if (lane == 1) xh1 = rval ? xr0[128] : 0.f;
            const float* wb = wbase0 + (size_t)ei0 * 3;
            #pragma unroll
            for (int j = 0; j < 3; j++)
                wr4[j] = *(const float4*)&wb[(size_t)wm[j] * KCONV + wq4[j]];
        }

        // ---- compute slab in buf ----
        #pragma unroll
        for (int k = 0; k < 8; k++) {
            // B windows: need Xs[k][3 + base + c], c=0..5, base = tx*4 (+64)
            const float* xk = &Xs[buf][k][0];
            float4 p0 = *(const float4*)&xk[tx * 4];
            float4 q0 = *(const float4*)&xk[tx * 4 + 4];
            float  s0 = xk[tx * 4 + 8];
            float4 p1 = *(const float4*)&xk[tx * 4 + 64];
            float4 q1 = *(const float4*)&xk[tx * 4 + 68];
            float  s1 = xk[tx * 4 + 72];
            float w0[6] = {p0.w, q0.x, q0.y, q0.z, q0.w, s0};
            float w1[6] = {p1.w, q1.x, q1.y, q1.z, q1.w, s1};

            #pragma unroll
            for (int dk = 0; dk < 3; dk++) {
                const float* wk = &Ws[buf][(k * 3 + dk) * 128];
                float4 a0 = *(const float4*)&wk[ty * 4];
                float4 a1 = *(const float4*)&wk[ty * 4 + 64];
                float av[8] = {a0.x, a0.y, a0.z, a0.w, a1.x, a1.y, a1.z, a1.w};
                #pragma unroll
                for (int ii = 0; ii < 8; ii++) {
                    #pragma unroll
                    for (int jj = 0; jj < 4; jj++)
                        acc[ii][jj]     += av[ii] * w0[jj + dk];
                    #pragma unroll
                    for (int jj = 0; jj < 4; jj++)
                        acc[ii][jj + 4] += av[ii] * w1[jj + dk];
                }
            }
        }

        if (more) {
            const int nb = buf ^ 1;
            Xs[nb][xrow][4 + lane * 4 + 0] = xr.x;
            Xs[nb][xrow][4 + lane * 4 + 1] = xr.y;
            Xs[nb][xrow][4 + lane * 4 + 2] = xr.z;
            Xs[nb][xrow][4 + lane * 4 + 3] = xr.w;
            if (lane == 0) Xs[nb][xrow][3]   = xh0;
            if (lane == 1) Xs[nb][xrow][132] = xh1;
            #pragma unroll
            for (int j = 0; j < 3; j++) {
                Ws[nb][(wq4[j] + 0) * 128 + wm[j]] = wr4[j].x;
                Ws[nb][(wq4[j] + 1) * 128 + wm[j]] = wr4[j].y;
                Ws[nb][(wq4[j] + 2) * 128 + wm[j]] = wr4[j].z;
                Ws[nb][(wq4[j] + 3) * 128 + wm[j]] = wr4[j].w;
            }
            buf = nb;
            __syncthreads();
        }
    }

    // Epilogue: bias + relu + residual, write per MODE layout
    #pragma unroll
    for (int ii = 0; ii < 8; ii++) {
        int m = m0 + ty * 4 + ((ii < 4) ? ii : (64 + ii - 4));
        float bvv = bias[m];
        #pragma unroll
        for (int jj = 0; jj < 8; jj++) {
            int t2 = t0 + tx * 4 + ((jj < 4) ? jj : (64 + jj - 4));
            float res = xin[((size_t)b * Ee + m) * Tt + t2];
            float v = acc[ii][jj] + bvv;
            v = (v > 0.f ? v : 0.f) + res;
            if (MODE == 0) out[((size_t)b * Ee + m) * Tt + t2] = v;
            else           out[((size_t)b * Tt + t2) * Ee + m] = v;
        }
    }
}

// ---------------------------------------------------------------------------
// Span max gather: maxed[p][:] = max over head span + max over tail span
// ---------------------------------------------------------------------------
__global__ __launch_bounds__(128) void span_kernel(
    const int* __restrict__ bidx,
    const int* __restrict__ hidx, const int* __restrict__ hspan,
    const int* __restrict__ tidx, const int* __restrict__ tspan)
{
    const int p  = blockIdx.x;
    const int e4 = threadIdx.x;                 // float4 index over E/4 = 128
    const int b  = bidx[p];
    const float4* __restrict__ base = (const float4*)g_xbte + (size_t)b * Tt * (Ee / 4);

    const int h0 = hidx[p], hs = hspan[p];
    const int t0 = tidx[p], ts = tspan[p];

    float4 hm = make_float4(-INFINITY, -INFINITY, -INFINITY, -INFINITY);
    for (int s = 0; s < hs; s++) {
        float4 v = base[(size_t)(h0 + s) * (Ee / 4) + e4];
        hm.x = fmaxf(hm.x, v.x); hm.y = fmaxf(hm.y, v.y);
        hm.z = fmaxf(hm.z, v.z); hm.w = fmaxf(hm.w, v.w);
    }
    float4 tm = make_float4(-INFINITY, -INFINITY, -INFINITY, -INFINITY);
    for (int s = 0; s < ts; s++) {
        float4 v = base[(size_t)(t0 + s) * (Ee / 4) + e4];
        tm.x = fmaxf(tm.x, v.x); tm.y = fmaxf(tm.y, v.y);
        tm.z = fmaxf(tm.z, v.z); tm.w = fmaxf(tm.w, v.w);
    }
    float4 o = make_float4(hm.x + tm.x, hm.y + tm.y, hm.z + tm.z, hm.w + tm.w);
    ((float4*)g_maxed)[(size_t)p * (Ee / 4) + e4] = o;
}

// ---------------------------------------------------------------------------
// NT SGEMM with double-buffered smem:
//   C[m][n] = act( sum_k A[m][k] * Bm[n][k] + bias[n] )
// 128x128x8 tile, 256 threads, 8x8 per thread. N bounds-checked.
// ---------------------------------------------------------------------------
template<bool RELU>
__global__ __launch_bounds__(256, 2) void gemm_nt_kernel(
    const float* __restrict__ A,
    const float* __restrict__ Bm,
    const float* __restrict__ bias,
    float* __restrict__ C,
    int M, int N, int K)
{
    __shared__ float As[2][8][128];
    __shared__ float Bs[2][8][128];

    const int tid = threadIdx.x;
    const int n0 = blockIdx.x * 128;
    const int m0 = blockIdx.y * 128;
    const int tx = tid & 15;
    const int ty = tid >> 4;

    float acc[8][8];
    #pragma unroll
    for (int i = 0; i < 8; i++)
        #pragma unroll
        for (int j = 0; j < 8; j++) acc[i][j] = 0.f;

    const int r = tid >> 1;
    const int s = (tid & 1) * 4;
    const bool bvalid = (n0 + r) < N;
    const float* __restrict__ Arow = A  + (size_t)(m0 + r) * K + s;
    const float* __restrict__ Brow = Bm + (size_t)(n0 + r) * K + s;

    float4 a_n, b_n;

    a_n = *(const float4*)&Arow[0];
    b_n = bvalid ? *(const float4*)&Brow[0] : make_float4(0.f, 0.f, 0.f, 0.f);
    As[0][s + 0][r] = a_n.x; As[0][s + 1][r] = a_n.y;
    As[0][s + 2][r] = a_n.z; As[0][s + 3][r] = a_n.w;
    Bs[0][s + 0][r] = b_n.x; Bs[0][s + 1][r] = b_n.y;
    Bs[0][s + 2][r] = b_n.z; Bs[0][s + 3][r] = b_n.w;
    __syncthreads();

    int buf = 0;
    for (int k0 = 8; k0 <= K; k0 += 8) {
        const bool more = (k0 < K);
        if (more) {
            a_n = *(const float4*)&Arow[k0];
            b_n = bvalid ? *(const float4*)&Brow[k0] : make_float4(0.f, 0.f, 0.f, 0.f);
        }

        #pragma unroll
        for (int k = 0; k < 8; k++) {
            float4 a0 = *(const float4*)&As[buf][k][ty * 4];
            float4 a1 = *(const float4*)&As[buf][k][ty * 4 + 64];
            float4 b0 = *(const float4*)&Bs[buf][k][tx * 4];
            float4 b1 = *(const float4*)&Bs[buf][k][tx * 4 + 64];
            float av[8] = {a0.x, a0.y, a0.z, a0.w, a1.x, a1.y, a1.z, a1.w};
            float bv[8] = {b0.x, b0.y, b0.z, b0.w, b1.x, b1.y, b1.z, b1.w};
            #pragma unroll
            for (int ii = 0; ii < 8; ii++)
                #pragma unroll
                for (int jj = 0; jj < 8; jj++)
                    acc[ii][jj] += av[ii] * bv[jj];
        }

        if (more) {
            int nb = buf ^ 1;
            As[nb][s + 0][r] = a_n.x; As[nb][s + 1][r] = a_n.y;
            As[nb][s + 2][r] = a_n.z; As[nb][s + 3][r] = a_n.w;
            Bs[nb][s + 0][r] = b_n.x; Bs[nb][s + 1][r] = b_n.y;
            Bs[nb][s + 2][r] = b_n.z; Bs[nb][s + 3][r] = b_n.w;
            buf = nb;
            __syncthreads();
        }
    }

    #pragma unroll
    for (int ii = 0; ii < 8; ii++) {
        int m = m0 + ty * 4 + ((ii < 4) ? ii : (64 + ii - 4));
        #pragma unroll
        for (int jj = 0; jj < 8; jj++) {
            int nn = n0 + tx * 4 + ((jj < 4) ? jj : (64 + jj - 4));
            if (nn < N) {
                float v = acc[ii][jj] + bias[nn];
                if (RELU) v = (v > 0.f) ? v : 0.f;
                C[(size_t)m * N + nn] = v;
            }
        }
    }
}

// ---------------------------------------------------------------------------
// Pack the remaining outputs: trig_attn (passthrough) and rel_labels (as float)
// ---------------------------------------------------------------------------
__global__ void pack_kernel(const float* __restrict__ trig,
                            const int* __restrict__ labels,
                            float* __restrict__ out, int out_size)
{
    int i = blockIdx.x * blockDim.x + threadIdx.x;
    const int PR = Pp * Rr;
    const int BT = Bb * Tt;
    if (out_size >= PR + BT && i < BT)        out[PR + i]      = trig[i];
    if (out_size >= PR + BT + Pp && i < Pp)   out[PR + BT + i] = (float)labels[i];
}

// ---------------------------------------------------------------------------
extern "C" void kernel_launch(void* const* d_in, const int* in_sizes, int n_in,
                              void* d_out, int out_size)
{
    const float* x     = (const float*)d_in[0];
    const float* trig  = (const float*)d_in[1];
    const int*   bidx  = (const int*)  d_in[2];
    const int*   hidx  = (const int*)  d_in[3];
    const int*   hspan = (const int*)  d_in[4];
    const int*   tidx  = (const int*)  d_in[5];
    const int*   tspan = (const int*)  d_in[6];
    const int*   labels= (const int*)  d_in[7];
    const float* c1w   = (const float*)d_in[8];
    const float* c1b   = (const float*)d_in[9];
    const float* c2w   = (const float*)d_in[10];
    const float* c2b   = (const float*)d_in[11];
    const float* w1    = (const float*)d_in[12];
    const float* b1    = (const float*)d_in[13];
    const float* w2    = (const float*)d_in[14];
    const float* b2    = (const float*)d_in[15];
    const float* wr    = (const float*)d_in[16];
    const float* br    = (const float*)d_in[17];
    float* out = (float*)d_out;

    float *pmaxed, *ph1, *ph2;
    cudaGetSymbolAddress((void**)&pmaxed, g_maxed);
    cudaGetSymbolAddress((void**)&ph1,    g_h1);
    cudaGetSymbolAddress((void**)&ph2,    g_h2);

    // Conv block 1: (B,E,T) -> g_x1 (B,E,T)
    {
        dim3 grid((Bb * Tt) / 128, Ee / 128);   // 64 x 4
        conv_block_kernel<0><<<grid, 256>>>(x, c1w, c1b);
    }
    // Conv block 2: g_x1 -> g_xbte (B,T,E)
    {
        dim3 grid((Bb * Tt) / 128, Ee / 128);
        conv_block_kernel<1><<<grid, 256>>>(nullptr, c2w, c2b);
    }
    // Span max gather
    span_kernel<<<Pp, 128>>>(bidx, hidx, hspan, tidx, tspan);

    // FC1: (P,512) x (1024,512)^T -> (P,1024), relu
    {
        dim3 grid(Hh / 128, Pp / 128);
        gemm_nt_kernel<true><<<grid, 256>>>(pmaxed, w1, b1, ph1, Pp, Hh, Ee);
    }
    // FC2: (P,1024) x (1024,1024)^T -> (P,1024), relu
    {
        dim3 grid(Hh / 128, Pp / 128);
        gemm_nt_kernel<true><<<grid, 256>>>(ph1, w2, b2, ph2, Pp, Hh, Hh);
    }
    // FC3: (P,1024) x (32,1024)^T -> (P,32), no act, straight into d_out
    {
        dim3 grid(1, Pp / 128);
        gemm_nt_kernel<false><<<grid, 256>>>(ph2, wr, br, out, Pp, Rr, Hh);
    }
    // trig_attn + rel_labels passthrough
    pack_kernel<<<(8192 + 255) / 256, 256>>>(trig, labels, out, out_size);
}

// round 4
// speedup vs baseline: 1.3043x; 1.0886x over previous
#include <cuda_runtime.h>
#include <math.h>

// Problem constants
#define Bb 16
#define Ee 512
#define Tt 512
#define Hh 1024
#define Rr 32
#define Pp 8192
#define Ww 3
#define KCONV (Ee*Ww)   // 1536
#define KSPLIT 4

// Scratch (device globals: allocation-free per harness rules)
__device__ float g_x1[Bb*Ee*Tt];     // after conv block 1, layout (B,E,T)
__device__ float g_xbte[Bb*Tt*Ee];   // after conv block 2, layout (B,T,E)
__device__ float g_maxed[Pp*Ee];     // span-max head+tail, (P,E)
__device__ float g_h1[Pp*Hh];
__device__ float g_h2[Pp*Hh];
__device__ float g_fc3p[KSPLIT*Pp*Rr]; // FC3 split-K partials

// ---------------------------------------------------------------------------
// Residual conv block as halo-tile 3-tap GEMM, double-buffered.
// (unchanged from round 3)
// ---------------------------------------------------------------------------
template<int MODE>
__global__ __launch_bounds__(256, 2) void conv_block_kernel(
    const float* __restrict__ xin_param,
    const float* __restrict__ w,
    const float* __restrict__ bias)
{
    const float* __restrict__ xin = (MODE == 0) ? xin_param : (const float*)g_x1;
    float* __restrict__ out       = (MODE == 0) ? (float*)g_x1 : (float*)g_xbte;

    __shared__ float Xs[2][8][136];
    __shared__ float Ws[2][24*128];

    const int tid = threadIdx.x;
    const int n0 = blockIdx.x * 128;
    const int m0 = blockIdx.y * 128;
    const int b  = n0 >> 9;
    const int t0 = n0 & 511;
    const int tx = tid & 15;
    const int ty = tid >> 4;

    float acc[8][8];
    #pragma unroll
    for (int i = 0; i < 8; i++)
        #pragma unroll
        for (int j = 0; j < 8; j++) acc[i][j] = 0.f;

    const int xrow = tid >> 5;
    const int lane = tid & 31;
    const bool lval = (t0 > 0);
    const bool rval = (t0 + 128 < Tt);
    const float* __restrict__ xrow_base0 = xin + ((size_t)b * Ee + xrow) * Tt + t0;

    int wm[3], wq4[3];
    #pragma unroll
    for (int j = 0; j < 3; j++) {
        int f4idx = tid + 256 * j;
        wm[j]  = f4idx / 6;
        wq4[j] = (f4idx % 6) * 4;
    }
    const float* __restrict__ wbase0 = w + (size_t)m0 * KCONV;

    float4 xr; float xh0 = 0.f, xh1 = 0.f;
    float4 wr4[3];

    {
        const float* xr0 = xrow_base0;
        xr = *(const float4*)&xr0[lane * 4];
        if (lane == 0) xh0 = lval ? xr0[-1]  : 0.f;
        if (lane == 1) xh1 = rval ? xr0[128] : 0.f;
        #pragma unroll
        for (int j = 0; j < 3; j++)
            wr4[j] = *(const float4*)&wbase0[(size_t)wm[j] * KCONV + wq4[j]];

        Xs[0][xrow][4 + lane * 4 + 0] = xr.x;
        Xs[0][xrow][4 + lane * 4 + 1] = xr.y;
        Xs[0][xrow][4 + lane * 4 + 2] = xr.z;
        Xs[0][xrow][4 + lane * 4 + 3] = xr.w;
        if (lane == 0) Xs[0][xrow][3]   = xh0;
        if (lane == 1) Xs[0][xrow][132] = xh1;
        #pragma unroll
        for (int j = 0; j < 3; j++) {
            Ws[0][(wq4[j] + 0) * 128 + wm[j]] = wr4[j].x;
            Ws[0][(wq4[j] + 1) * 128 + wm[j]] = wr4[j].y;
            Ws[0][(wq4[j] + 2) * 128 + wm[j]] = wr4[j].z;
            Ws[0][(wq4[j] + 3) * 128 + wm[j]] = wr4[j].w;
        }
    }
    __syncthreads();

    int buf = 0;
    for (int ei0 = 8; ei0 <= Ee; ei0 += 8) {
        const bool more = (ei0 < Ee);
        if (more) {
            const float* xr0 = xrow_base0 + (size_t)ei0 * Tt;
            xr = *(const float4*)&xr0[lane * 4];
            if (lane == 0) xh0 = lval ? xr0[-1]  : 0.f;
            if (lane == 1) xh1 = rval ? xr0[128] : 0.f;
            const float* wb = wbase0 + (size_t)ei0 * 3;
            #pragma unroll
            for (int j = 0; j < 3; j++)
                wr4[j] = *(const float4*)&wb[(size_t)wm[j] * KCONV + wq4[j]];
        }

        #pragma unroll
        for (int k = 0; k < 8; k++) {
            const float* xk = &Xs[buf][k][0];
            float4 p0 = *(const float4*)&xk[tx * 4];
            float4 q0 = *(const float4*)&xk[tx * 4 + 4];
            float  s0 = xk[tx * 4 + 8];
            float4 p1 = *(const float4*)&xk[tx * 4 + 64];
            float4 q1 = *(const float4*)&xk[tx * 4 + 68];
            float  s1 = xk[tx * 4 + 72];
            float w0[6] = {p0.w, q0.x, q0.y, q0.z, q0.w, s0};
            float w1[6] = {p1.w, q1.x, q1.y, q1.z, q1.w, s1};

            #pragma unroll
            for (int dk = 0; dk < 3; dk++) {
                const float* wk = &Ws[buf][(k * 3 + dk) * 128];
                float4 a0 = *(const float4*)&wk[ty * 4];
                float4 a1 = *(const float4*)&wk[ty * 4 + 64];
                float av[8] = {a0.x, a0.y, a0.z, a0.w, a1.x, a1.y, a1.z, a1.w};
                #pragma unroll
                for (int ii = 0; ii < 8; ii++) {
                    #pragma unroll
                    for (int jj = 0; jj < 4; jj++)
                        acc[ii][jj]     += av[ii] * w0[jj + dk];
                    #pragma unroll
                    for (int jj = 0; jj < 4; jj++)
                        acc[ii][jj + 4] += av[ii] * w1[jj + dk];
                }
            }
        }

        if (more) {
            const int nb = buf ^ 1;
            Xs[nb][xrow][4 + lane * 4 + 0] = xr.x;
            Xs[nb][xrow][4 + lane * 4 + 1] = xr.y;
            Xs[nb][xrow][4 + lane * 4 + 2] = xr.z;
            Xs[nb][xrow][4 + lane * 4 + 3] = xr.w;
            if (lane == 0) Xs[nb][xrow][3]   = xh0;
            if (lane == 1) Xs[nb][xrow][132] = xh1;
            #pragma unroll
            for (int j = 0; j < 3; j++) {
                Ws[nb][(wq4[j] + 0) * 128 + wm[j]] = wr4[j].x;
                Ws[nb][(wq4[j] + 1) * 128 + wm[j]] = wr4[j].y;
                Ws[nb][(wq4[j] + 2) * 128 + wm[j]] = wr4[j].z;
                Ws[nb][(wq4[j] + 3) * 128 + wm[j]] = wr4[j].w;
            }
            buf = nb;
            __syncthreads();
        }
    }

    #pragma unroll
    for (int ii = 0; ii < 8; ii++) {
        int m = m0 + ty * 4 + ((ii < 4) ? ii : (64 + ii - 4));
        float bvv = bias[m];
        #pragma unroll
        for (int jj = 0; jj < 8; jj++) {
            int t2 = t0 + tx * 4 + ((jj < 4) ? jj : (64 + jj - 4));
            float res = xin[((size_t)b * Ee + m) * Tt + t2];
            float v = acc[ii][jj] + bvv;
            v = (v > 0.f ? v : 0.f) + res;
            if (MODE == 0) out[((size_t)b * Ee + m) * Tt + t2] = v;
            else           out[((size_t)b * Tt + t2) * Ee + m] = v;
        }
    }
}

// ---------------------------------------------------------------------------
// Span max gather
// ---------------------------------------------------------------------------
__global__ __launch_bounds__(128) void span_kernel(
    const int* __restrict__ bidx,
    const int* __restrict__ hidx, const int* __restrict__ hspan,
    const int* __restrict__ tidx, const int* __restrict__ tspan)
{
    const int p  = blockIdx.x;
    const int e4 = threadIdx.x;
    const int b  = bidx[p];
    const float4* __restrict__ base = (const float4*)g_xbte + (size_t)b * Tt * (Ee / 4);

    const int h0 = hidx[p], hs = hspan[p];
    const int t0 = tidx[p], ts = tspan[p];

    float4 hm = make_float4(-INFINITY, -INFINITY, -INFINITY, -INFINITY);
    for (int s = 0; s < hs; s++) {
        float4 v = base[(size_t)(h0 + s) * (Ee / 4) + e4];
        hm.x = fmaxf(hm.x, v.x); hm.y = fmaxf(hm.y, v.y);
        hm.z = fmaxf(hm.z, v.z); hm.w = fmaxf(hm.w, v.w);
    }
    float4 tm = make_float4(-INFINITY, -INFINITY, -INFINITY, -INFINITY);
    for (int s = 0; s < ts; s++) {
        float4 v = base[(size_t)(t0 + s) * (Ee / 4) + e4];
        tm.x = fmaxf(tm.x, v.x); tm.y = fmaxf(tm.y, v.y);
        tm.z = fmaxf(tm.z, v.z); tm.w = fmaxf(tm.w, v.w);
    }
    float4 o = make_float4(hm.x + tm.x, hm.y + tm.y, hm.z + tm.z, hm.w + tm.w);
    ((float4*)g_maxed)[(size_t)p * (Ee / 4) + e4] = o;
}

// ---------------------------------------------------------------------------
// NT SGEMM with double-buffered smem (for FC1/FC2; N multiple of 128)
// ---------------------------------------------------------------------------
template<bool RELU>
__global__ __launch_bounds__(256, 2) void gemm_nt_kernel(
    const float* __restrict__ A,
    const float* __restrict__ Bm,
    const float* __restrict__ bias,
    float* __restrict__ C,
    int M, int N, int K)
{
    __shared__ float As[2][8][128];
    __shared__ float Bs[2][8][128];

    const int tid = threadIdx.x;
    const int n0 = blockIdx.x * 128;
    const int m0 = blockIdx.y * 128;
    const int tx = tid & 15;
    const int ty = tid >> 4;

    float acc[8][8];
    #pragma unroll
    for (int i = 0; i < 8; i++)
        #pragma unroll
        for (int j = 0; j < 8; j++) acc[i][j] = 0.f;

    const int r = tid >> 1;
    const int s = (tid & 1) * 4;
    const float* __restrict__ Arow = A  + (size_t)(m0 + r) * K + s;
    const float* __restrict__ Brow = Bm + (size_t)(n0 + r) * K + s;

    float4 a_n, b_n;

    a_n = *(const float4*)&Arow[0];
    b_n = *(const float4*)&Brow[0];
    As[0][s + 0][r] = a_n.x; As[0][s + 1][r] = a_n.y;
    As[0][s + 2][r] = a_n.z; As[0][s + 3][r] = a_n.w;
    Bs[0][s + 0][r] = b_n.x; Bs[0][s + 1][r] = b_n.y;
    Bs[0][s + 2][r] = b_n.z; Bs[0][s + 3][r] = b_n.w;
    __syncthreads();

    int buf = 0;
    for (int k0 = 8; k0 <= K; k0 += 8) {
        const bool more = (k0 < K);
        if (more) {
            a_n = *(const float4*)&Arow[k0];
            b_n = *(const float4*)&Brow[k0];
        }

        #pragma unroll
        for (int k = 0; k < 8; k++) {
            float4 a0 = *(const float4*)&As[buf][k][ty * 4];
            float4 a1 = *(const float4*)&As[buf][k][ty * 4 + 64];
            float4 b0 = *(const float4*)&Bs[buf][k][tx * 4];
            float4 b1 = *(const float4*)&Bs[buf][k][tx * 4 + 64];
            float av[8] = {a0.x, a0.y, a0.z, a0.w, a1.x, a1.y, a1.z, a1.w};
            float bv[8] = {b0.x, b0.y, b0.z, b0.w, b1.x, b1.y, b1.z, b1.w};
            #pragma unroll
            for (int ii = 0; ii < 8; ii++)
                #pragma unroll
                for (int jj = 0; jj < 8; jj++)
                    acc[ii][jj] += av[ii] * bv[jj];
        }

        if (more) {
            int nb = buf ^ 1;
            As[nb][s + 0][r] = a_n.x; As[nb][s + 1][r] = a_n.y;
            As[nb][s + 2][r] = a_n.z; As[nb][s + 3][r] = a_n.w;
            Bs[nb][s + 0][r] = b_n.x; Bs[nb][s + 1][r] = b_n.y;
            Bs[nb][s + 2][r] = b_n.z; Bs[nb][s + 3][r] = b_n.w;
            buf = nb;
            __syncthreads();
        }
    }

    #pragma unroll
    for (int ii = 0; ii < 8; ii++) {
        int m = m0 + ty * 4 + ((ii < 4) ? ii : (64 + ii - 4));
        #pragma unroll
        for (int jj = 0; jj < 8; jj++) {
            int nn = n0 + tx * 4 + ((jj < 4) ? jj : (64 + jj - 4));
            float v = acc[ii][jj] + bias[nn];
            if (RELU) v = (v > 0.f) ? v : 0.f;
            C[(size_t)m * N + nn] = v;
        }
    }
}

// ---------------------------------------------------------------------------
// FC3 split-K GEMM: partial[s][m][n] = sum_{k in chunk s} A[m][k] * Wr[n][k]
// Tile: 128(M) x 32(N) x 8, K-chunk = 1024/KSPLIT = 256. grid (KSPLIT, M/128).
// 256 threads, each computes 4x4 accs (ty: 32 M-groups of 4, tx: 8 N-groups of 4).
// Deterministic: fixed partial buffer, no atomics.
// ---------------------------------------------------------------------------
__global__ __launch_bounds__(256, 2) void fc3_splitk_kernel(
    const float* __restrict__ A,      // (P, Hh)
    const float* __restrict__ Wr)     // (Rr, Hh)
{
    __shared__ float As[2][8][128];
    __shared__ float Bs[2][8][32];

    const int tid = threadIdx.x;
    const int ks  = blockIdx.x;            // K-split index
    const int m0  = blockIdx.y * 128;
    const int kbeg = ks * (Hh / KSPLIT);   // 256-chunk
    const int tx = tid & 7;                // N group (0..7)
    const int ty = tid >> 3;               // M group (0..31)

    float acc[4][4];
    #pragma unroll
    for (int i = 0; i < 4; i++)
        #pragma unroll
        for (int j = 0; j < 4; j++) acc[i][j] = 0.f;

    const int r = tid >> 1;
    const int s = (tid & 1) * 4;
    const float* __restrict__ Arow = A + (size_t)(m0 + r) * Hh + kbeg + s;
    // B loaders: threads 0..63
    const int br = tid >> 1;               // reuse r for A; for B use tid<64 mapping
    const float* __restrict__ Brow = Wr + (size_t)(tid >> 1) * Hh + kbeg + ((tid & 1) * 4);

    float4 a_n; float4 b_n = make_float4(0.f,0.f,0.f,0.f);

    a_n = *(const float4*)&Arow[0];
    if (tid < 64) b_n = *(const float4*)&Brow[0];
    As[0][s + 0][r] = a_n.x; As[0][s + 1][r] = a_n.y;
    As[0][s + 2][r] = a_n.z; As[0][s + 3][r] = a_n.w;
    if (tid < 64) {
        int bn = tid >> 1, bs = (tid & 1) * 4;
        Bs[0][bs + 0][bn] = b_n.x; Bs[0][bs + 1][bn] = b_n.y;
        Bs[0][bs + 2][bn] = b_n.z; Bs[0][bs + 3][bn] = b_n.w;
    }
    __syncthreads();

    int buf = 0;
    const int KC = Hh / KSPLIT;
    for (int k0 = 8; k0 <= KC; k0 += 8) {
        const bool more = (k0 < KC);
        if (more) {
            a_n = *(const float4*)&Arow[k0];
            if (tid < 64) b_n = *(const float4*)&Brow[k0];
        }

        #pragma unroll
        for (int k = 0; k < 8; k++) {
            float4 a0 = *(const float4*)&As[buf][k][ty * 4];
            float4 b0 = *(const float4*)&Bs[buf][k][tx * 4];
            float av[4] = {a0.x, a0.y, a0.z, a0.w};
            float bv[4] = {b0.x, b0.y, b0.z, b0.w};
            #pragma unroll
            for (int ii = 0; ii < 4; ii++)
                #pragma unroll
                for (int jj = 0; jj < 4; jj++)
                    acc[ii][jj] += av[ii] * bv[jj];
        }

        if (more) {
            int nb = buf ^ 1;
            As[nb][s + 0][r] = a_n.x; As[nb][s + 1][r] = a_n.y;
            As[nb][s + 2][r] = a_n.z; As[nb][s + 3][r] = a_n.w;
            if (tid < 64) {
                int bn = tid >> 1, bs = (tid & 1) * 4;
                Bs[nb][bs + 0][bn] = b_n.x; Bs[nb][bs + 1][bn] = b_n.y;
                Bs[nb][bs + 2][bn] = b_n.z; Bs[nb][bs + 3][bn] = b_n.w;
            }
            buf = nb;
            __syncthreads();
        }
    }

    float* __restrict__ part = (float*)g_fc3p + (size_t)ks * Pp * Rr;
    #pragma unroll
    for (int ii = 0; ii < 4; ii++) {
        int m = m0 + ty * 4 + ii;
        #pragma unroll
        for (int jj = 0; jj < 4; jj++) {
            int nn = tx * 4 + jj;
            part[(size_t)m * Rr + nn] = acc[ii][jj];
        }
    }
}

// Reduce split-K partials + bias -> d_out (P x R)
__global__ void fc3_reduce_kernel(const float* __restrict__ br,
                                  float* __restrict__ out)
{
    int i = blockIdx.x * blockDim.x + threadIdx.x;   // over P*R
    if (i < Pp * Rr) {
        const float* p = (const float*)g_fc3p;
        float v = p[i] + p[i + Pp*Rr] + p[i + 2*Pp*Rr] + p[i + 3*Pp*Rr];
        out[i] = v + br[i & (Rr - 1)];
    }
}

// ---------------------------------------------------------------------------
// Pack the remaining outputs
// ---------------------------------------------------------------------------
__global__ void pack_kernel(const float* __restrict__ trig,
                            const int* __restrict__ labels,
                            float* __restrict__ out, int out_size)
{
    int i = blockIdx.x * blockDim.x + threadIdx.x;
    const int PR = Pp * Rr;
    const int BT = Bb * Tt;
    if (out_size >= PR + BT && i < BT)        out[PR + i]      = trig[i];
    if (out_size >= PR + BT + Pp && i < Pp)   out[PR + BT + i] = (float)labels[i];
}

// ---------------------------------------------------------------------------
extern "C" void kernel_launch(void* const* d_in, const int* in_sizes, int n_in,
                              void* d_out, int out_size)
{
    const float* x     = (const float*)d_in[0];
    const float* trig  = (const float*)d_in[1];
    const int*   bidx  = (const int*)  d_in[2];
    const int*   hidx  = (const int*)  d_in[3];
    const int*   hspan = (const int*)  d_in[4];
    const int*   tidx  = (const int*)  d_in[5];
    const int*   tspan = (const int*)  d_in[6];
    const int*   labels= (const int*)  d_in[7];
    const float* c1w   = (const float*)d_in[8];
    const float* c1b   = (const float*)d_in[9];
    const float* c2w   = (const float*)d_in[10];
    const float* c2b   = (const float*)d_in[11];
    const float* w1    = (const float*)d_in[12];
    const float* b1    = (const float*)d_in[13];
    const float* w2    = (const float*)d_in[14];
    const float* b2    = (const float*)d_in[15];
    const float* wr    = (const float*)d_in[16];
    const float* br    = (const float*)d_in[17];
    float* out = (float*)d_out;

    float *pmaxed, *ph1, *ph2;
    cudaGetSymbolAddress((void**)&pmaxed, g_maxed);
    cudaGetSymbolAddress((void**)&ph1,    g_h1);
    cudaGetSymbolAddress((void**)&ph2,    g_h2);

    // Conv block 1: (B,E,T) -> g_x1 (B,E,T)
    {
        dim3 grid((Bb * Tt) / 128, Ee / 128);
        conv_block_kernel<0><<<grid, 256>>>(x, c1w, c1b);
    }
    // Conv block 2: g_x1 -> g_xbte (B,T,E)
    {
        dim3 grid((Bb * Tt) / 128, Ee / 128);
        conv_block_kernel<1><<<grid, 256>>>(nullptr, c2w, c2b);
    }
    // Span max gather
    span_kernel<<<Pp, 128>>>(bidx, hidx, hspan, tidx, tspan);

    // FC1: (P,512) x (1024,512)^T -> (P,1024), relu
    {
        dim3 grid(Hh / 128, Pp / 128);
        gemm_nt_kernel<true><<<grid, 256>>>(pmaxed, w1, b1, ph1, Pp, Hh, Ee);
    }
    // FC2: (P,1024) x (1024,1024)^T -> (P,1024), relu
    {
        dim3 grid(Hh / 128, Pp / 128);
        gemm_nt_kernel<true><<<grid, 256>>>(ph1, w2, b2, ph2, Pp, Hh, Hh);
    }
    // FC3: split-K over 4 chunks, then reduce+bias into d_out
    {
        dim3 grid(KSPLIT, Pp / 128);
        fc3_splitk_kernel<<<grid, 256>>>(ph2, wr);
        fc3_reduce_kernel<<<(Pp * Rr + 255) / 256, 256>>>(br, out);
    }
    // trig_attn + rel_labels passthrough
    pack_kernel<<<(8192 + 255) / 256, 256>>>(trig, labels, out, out_size);
}

// round 5
// speedup vs baseline: 1.3749x; 1.0541x over previous
#include <cuda_runtime.h>
#include <math.h>

// Problem constants
#define Bb 16
#define Ee 512
#define Tt 512
#define Hh 1024
#define Rr 32
#define Pp 8192
#define Ww 3
#define KCONV (Ee*Ww)   // 1536
#define KSPLIT 4

typedef unsigned long long u64;

// Packed f32x2 helpers (SASS FFMA2 path — ptxas never auto-generates these)
#define FMA2(d, a, b) \
    asm("fma.rn.f32x2 %0, %1, %2, %0;" : "+l"(d) : "l"(a), "l"(b))
#define DUP2(d, s) \
    asm("mov.b64 %0, {%1, %1};" : "=l"(d) : "f"(s))
#define UNPK2(lo, hi, v) \
    asm("mov.b64 {%0, %1}, %2;" : "=f"(lo), "=f"(hi) : "l"(v))

// Scratch (device globals: allocation-free per harness rules)
__device__ float g_x1[Bb*Ee*Tt];     // after conv block 1, layout (B,E,T)
__device__ float g_xbte[Bb*Tt*Ee];   // after conv block 2, layout (B,T,E)
__device__ float g_maxed[Pp*Ee];     // span-max head+tail, (P,E)
__device__ float g_h1[Pp*Hh];
__device__ float g_h2[Pp*Hh];
__device__ float g_fc3p[KSPLIT*Pp*Rr]; // FC3 split-K partials

// ---------------------------------------------------------------------------
// Residual conv block: halo-tile 3-tap GEMM, double-buffered, FFMA2 inner.
//   y[b][eo][t] = relu( sum_{ei,dk} w[eo][ei][dk]*x[b][ei][t+dk-1] + bias[eo] ) + x[b][eo][t]
// Tile: 128(M=eo) x 128(N=t) x 8(ei). acc packed in pairs along M.
// MODE 0: read param x (B,E,T), write g_x1 (B,E,T)
// MODE 1: read g_x1,           write g_xbte (B,T,E)
// ---------------------------------------------------------------------------
template<int MODE>
__global__ __launch_bounds__(256, 2) void conv_block_kernel(
    const float* __restrict__ xin_param,
    const float* __restrict__ w,
    const float* __restrict__ bias)
{
    const float* __restrict__ xin = (MODE == 0) ? xin_param : (const float*)g_x1;
    float* __restrict__ out       = (MODE == 0) ? (float*)g_x1 : (float*)g_xbte;

    __shared__ __align__(16) float Xs[2][8][136];
    __shared__ __align__(16) float Ws[2][24*128];

    const int tid = threadIdx.x;
    const int n0 = blockIdx.x * 128;
    const int m0 = blockIdx.y * 128;
    const int b  = n0 >> 9;
    const int t0 = n0 & 511;
    const int tx = tid & 15;
    const int ty = tid >> 4;

    u64 acc2[4][8];
    #pragma unroll
    for (int i = 0; i < 4; i++)
        #pragma unroll
        for (int j = 0; j < 8; j++) acc2[i][j] = 0ULL;

    const int xrow = tid >> 5;
    const int lane = tid & 31;
    const bool lval = (t0 > 0);
    const bool rval = (t0 + 128 < Tt);
    const float* __restrict__ xrow_base0 = xin + ((size_t)b * Ee + xrow) * Tt + t0;

    int wm[3], wq4[3];
    #pragma unroll
    for (int j = 0; j < 3; j++) {
        int f4idx = tid + 256 * j;
        wm[j]  = f4idx / 6;
        wq4[j] = (f4idx % 6) * 4;
    }
    const float* __restrict__ wbase0 = w + (size_t)m0 * KCONV;

    float4 xr; float xh0 = 0.f, xh1 = 0.f;
    float4 wr4[3];

    {
        const float* xr0 = xrow_base0;
        xr = *(const float4*)&xr0[lane * 4];
        if (lane == 0) xh0 = lval ? xr0[-1]  : 0.f;
        if (lane == 1) xh1 = rval ? xr0[128] : 0.f;
        #pragma unroll
        for (int j = 0; j < 3; j++)
            wr4[j] = *(const float4*)&wbase0[(size_t)wm[j] * KCONV + wq4[j]];

        Xs[0][xrow][4 + lane * 4 + 0] = xr.x;
        Xs[0][xrow][4 + lane * 4 + 1] = xr.y;
        Xs[0][xrow][4 + lane * 4 + 2] = xr.z;
        Xs[0][xrow][4 + lane * 4 + 3] = xr.w;
        if (lane == 0) Xs[0][xrow][3]   = xh0;
        if (lane == 1) Xs[0][xrow][132] = xh1;
        #pragma unroll
        for (int j = 0; j < 3; j++) {
            Ws[0][(wq4[j] + 0) * 128 + wm[j]] = wr4[j].x;
            Ws[0][(wq4[j] + 1) * 128 + wm[j]] = wr4[j].y;
            Ws[0][(wq4[j] + 2) * 128 + wm[j]] = wr4[j].z;
            Ws[0][(wq4[j] + 3) * 128 + wm[j]] = wr4[j].w;
        }
    }
    __syncthreads();

    int buf = 0;
    for (int ei0 = 8; ei0 <= Ee; ei0 += 8) {
        const bool more = (ei0 < Ee);
        if (more) {
            const float* xr0 = xrow_base0 + (size_t)ei0 * Tt;
            xr = *(const float4*)&xr0[lane * 4];
            if (lane == 0) xh0 = lval ? xr0[-1]  : 0.f;
            if (lane == 1) xh1 = rval ? xr0[128] : 0.f;
            const float* wb = wbase0 + (size_t)ei0 * 3;
            #pragma unroll
            for (int j = 0; j < 3; j++)
                wr4[j] = *(const float4*)&wb[(size_t)wm[j] * KCONV + wq4[j]];
        }

        // ---- compute slab in buf (FFMA2) ----
        #pragma unroll
        for (int k = 0; k < 8; k++) {
            const float* xk = &Xs[buf][k][0];
            float4 p0 = *(const float4*)&xk[tx * 4];
            float4 q0 = *(const float4*)&xk[tx * 4 + 4];
            float  s0 = xk[tx * 4 + 8];
            float4 p1 = *(const float4*)&xk[tx * 4 + 64];
            float4 q1 = *(const float4*)&xk[tx * 4 + 68];
            float  s1 = xk[tx * 4 + 72];

            u64 w0d[6], w1d[6];
            DUP2(w0d[0], p0.w); DUP2(w0d[1], q0.x); DUP2(w0d[2], q0.y);
            DUP2(w0d[3], q0.z); DUP2(w0d[4], q0.w); DUP2(w0d[5], s0);
            DUP2(w1d[0], p1.w); DUP2(w1d[1], q1.x); DUP2(w1d[2], q1.y);
            DUP2(w1d[3], q1.z); DUP2(w1d[4], q1.w); DUP2(w1d[5], s1);

            #pragma unroll
            for (int dk = 0; dk < 3; dk++) {
                const float* wk = &Ws[buf][(k * 3 + dk) * 128];
                ulonglong2 A0 = *(const ulonglong2*)&wk[ty * 4];
                ulonglong2 A1 = *(const ulonglong2*)&wk[ty * 4 + 64];
                u64 av2[4] = {A0.x, A0.y, A1.x, A1.y};
                #pragma unroll
                for (int ii = 0; ii < 4; ii++) {
                    #pragma unroll
                    for (int jj = 0; jj < 4; jj++)
                        FMA2(acc2[ii][jj],     av2[ii], w0d[dk + jj]);
                    #pragma unroll
                    for (int jj = 0; jj < 4; jj++)
                        FMA2(acc2[ii][jj + 4], av2[ii], w1d[dk + jj]);
                }
            }
        }

        if (more) {
            const int nb = buf ^ 1;
            Xs[nb][xrow][4 + lane * 4 + 0] = xr.x;
            Xs[nb][xrow][4 + lane * 4 + 1] = xr.y;
            Xs[nb][xrow][4 + lane * 4 + 2] = xr.z;
            Xs[nb][xrow][4 + lane * 4 + 3] = xr.w;
            if (lane == 0) Xs[nb][xrow][3]   = xh0;
            if (lane == 1) Xs[nb][xrow][132] = xh1;
            #pragma unroll
            for (int j = 0; j < 3; j++) {
                Ws[nb][(wq4[j] + 0) * 128 + wm[j]] = wr4[j].x;
                Ws[nb][(wq4[j] + 1) * 128 + wm[j]] = wr4[j].y;
                Ws[nb][(wq4[j] + 2) * 128 + wm[j]] = wr4[j].z;
                Ws[nb][(wq4[j] + 3) * 128 + wm[j]] = wr4[j].w;
            }
            buf = nb;
            __syncthreads();
        }
    }

    // Epilogue: bias + relu + residual; each acc2 holds rows (m, m+1)
    #pragma unroll
    for (int ii = 0; ii < 4; ii++) {
        int m = m0 + ((ii < 2) ? ty * 4 + ii * 2 : 64 + ty * 4 + (ii - 2) * 2);
        float blo = bias[m], bhi = bias[m + 1];
        #pragma unroll
        for (int jj = 0; jj < 8; jj++) {
            int t2 = t0 + tx * 4 + ((jj < 4) ? jj : (64 + jj - 4));
            float lo, hi;
            UNPK2(lo, hi, acc2[ii][jj]);
            float rlo = xin[((size_t)b * Ee + m)     * Tt + t2];
            float rhi = xin[((size_t)b * Ee + m + 1) * Tt + t2];
            float vlo = lo + blo; vlo = (vlo > 0.f ? vlo : 0.f) + rlo;
            float vhi = hi + bhi; vhi = (vhi > 0.f ? vhi : 0.f) + rhi;
            if (MODE == 0) {
                out[((size_t)b * Ee + m)     * Tt + t2] = vlo;
                out[((size_t)b * Ee + m + 1) * Tt + t2] = vhi;
            } else {
                out[((size_t)b * Tt + t2) * Ee + m]     = vlo;
                out[((size_t)b * Tt + t2) * Ee + m + 1] = vhi;
            }
        }
    }
}

// ---------------------------------------------------------------------------
// Span max gather
// ---------------------------------------------------------------------------
__global__ __launch_bounds__(128) void span_kernel(
    const int* __restrict__ bidx,
    const int* __restrict__ hidx, const int* __restrict__ hspan,
    const int* __restrict__ tidx, const int* __restrict__ tspan)
{
    const int p  = blockIdx.x;
    const int e4 = threadIdx.x;
    const int b  = bidx[p];
    const float4* __restrict__ base = (const float4*)g_xbte + (size_t)b * Tt * (Ee / 4);

    const int h0 = hidx[p], hs = hspan[p];
    const int t0 = tidx[p], ts = tspan[p];

    float4 hm = make_float4(-INFINITY, -INFINITY, -INFINITY, -INFINITY);
    for (int s = 0; s < hs; s++) {
        float4 v = base[(size_t)(h0 + s) * (Ee / 4) + e4];
        hm.x = fmaxf(hm.x, v.x); hm.y = fmaxf(hm.y, v.y);
        hm.z = fmaxf(hm.z, v.z); hm.w = fmaxf(hm.w, v.w);
    }
    float4 tm = make_float4(-INFINITY, -INFINITY, -INFINITY, -INFINITY);
    for (int s = 0; s < ts; s++) {
        float4 v = base[(size_t)(t0 + s) * (Ee / 4) + e4];
        tm.x = fmaxf(tm.x, v.x); tm.y = fmaxf(tm.y, v.y);
        tm.z = fmaxf(tm.z, v.z); tm.w = fmaxf(tm.w, v.w);
    }
    float4 o = make_float4(hm.x + tm.x, hm.y + tm.y, hm.z + tm.z, hm.w + tm.w);
    ((float4*)g_maxed)[(size_t)p * (Ee / 4) + e4] = o;
}

// ---------------------------------------------------------------------------
// NT SGEMM, double-buffered, FFMA2 inner.
//   C[m][n] = act( sum_k A[m][k] * Bm[n][k] + bias[n] )
// 128x128x8 tile, 256 threads. acc packed in pairs along M.
// N must be a multiple of 128 (FC1/FC2 only).
// ---------------------------------------------------------------------------
template<bool RELU>
__global__ __launch_bounds__(256, 2) void gemm_nt_kernel(
    const float* __restrict__ A,
    const float* __restrict__ Bm,
    const float* __restrict__ bias,
    float* __restrict__ C,
    int M, int N, int K)
{
    __shared__ __align__(16) float As[2][8][128];
    __shared__ __align__(16) float Bs[2][8][128];

    const int tid = threadIdx.x;
    const int n0 = blockIdx.x * 128;
    const int m0 = blockIdx.y * 128;
    const int tx = tid & 15;
    const int ty = tid >> 4;

    u64 acc2[4][8];
    #pragma unroll
    for (int i = 0; i < 4; i++)
        #pragma unroll
        for (int j = 0; j < 8; j++) acc2[i][j] = 0ULL;

    const int r = tid >> 1;
    const int s = (tid & 1) * 4;
    const float* __restrict__ Arow = A  + (size_t)(m0 + r) * K + s;
    const float* __restrict__ Brow = Bm + (size_t)(n0 + r) * K + s;

    float4 a_n, b_n;

    a_n = *(const float4*)&Arow[0];
    b_n = *(const float4*)&Brow[0];
    As[0][s + 0][r] = a_n.x; As[0][s + 1][r] = a_n.y;
    As[0][s + 2][r] = a_n.z; As[0][s + 3][r] = a_n.w;
    Bs[0][s + 0][r] = b_n.x; Bs[0][s + 1][r] = b_n.y;
    Bs[0][s + 2][r] = b_n.z; Bs[0][s + 3][r] = b_n.w;
    __syncthreads();

    int buf = 0;
    for (int k0 = 8; k0 <= K; k0 += 8) {
        const bool more = (k0 < K);
        if (more) {
            a_n = *(const float4*)&Arow[k0];
            b_n = *(const float4*)&Brow[k0];
        }

        #pragma unroll
        for (int k = 0; k < 8; k++) {
            ulonglong2 A0 = *(const ulonglong2*)&As[buf][k][ty * 4];
            ulonglong2 A1 = *(const ulonglong2*)&As[buf][k][ty * 4 + 64];
            u64 av2[4] = {A0.x, A0.y, A1.x, A1.y};
            float4 b0 = *(const float4*)&Bs[buf][k][tx * 4];
            float4 b1 = *(const float4*)&Bs[buf][k][tx * 4 + 64];
            u64 bd[8];
            DUP2(bd[0], b0.x); DUP2(bd[1], b0.y); DUP2(bd[2], b0.z); DUP2(bd[3], b0.w);
            DUP2(bd[4], b1.x); DUP2(bd[5], b1.y); DUP2(bd[6], b1.z); DUP2(bd[7], b1.w);
            #pragma unroll
            for (int ii = 0; ii < 4; ii++)
                #pragma unroll
                for (int jj = 0; jj < 8; jj++)
                    FMA2(acc2[ii][jj], av2[ii], bd[jj]);
        }

        if (more) {
            int nb = buf ^ 1;
            As[nb][s + 0][r] = a_n.x; As[nb][s + 1][r] = a_n.y;
            As[nb][s + 2][r] = a_n.z; As[nb][s + 3][r] = a_n.w;
            Bs[nb][s + 0][r] = b_n.x; Bs[nb][s + 1][r] = b_n.y;
            Bs[nb][s + 2][r] = b_n.z; Bs[nb][s + 3][r] = b_n.w;
            buf = nb;
            __syncthreads();
        }
    }

    #pragma unroll
    for (int ii = 0; ii < 4; ii++) {
        int m = m0 + ((ii < 2) ? ty * 4 + ii * 2 : 64 + ty * 4 + (ii - 2) * 2);
        #pragma unroll
        for (int jj = 0; jj < 8; jj++) {
            int nn = n0 + tx * 4 + ((jj < 4) ? jj : (64 + jj - 4));
            float lo, hi;
            UNPK2(lo, hi, acc2[ii][jj]);
            float bv = bias[nn];
            float vlo = lo + bv;
            float vhi = hi + bv;
            if (RELU) { vlo = (vlo > 0.f) ? vlo : 0.f; vhi = (vhi > 0.f) ? vhi : 0.f; }
            C[(size_t)m * N + nn]       = vlo;
            C[(size_t)(m + 1) * N + nn] = vhi;
        }
    }
}

// ---------------------------------------------------------------------------
// FC3 split-K GEMM (scalar FFMA; ~15us total, not worth the FFMA2 risk)
// ---------------------------------------------------------------------------
__global__ __launch_bounds__(256, 2) void fc3_splitk_kernel(
    const float* __restrict__ A,      // (P, Hh)
    const float* __restrict__ Wr)     // (Rr, Hh)
{
    __shared__ float As[2][8][128];
    __shared__ float Bs[2][8][32];

    const int tid = threadIdx.x;
    const int ks  = blockIdx.x;
    const int m0  = blockIdx.y * 128;
    const int kbeg = ks * (Hh / KSPLIT);
    const int tx = tid & 7;
    const int ty = tid >> 3;

    float acc[4][4];
    #pragma unroll
    for (int i = 0; i < 4; i++)
        #pragma unroll
        for (int j = 0; j < 4; j++) acc[i][j] = 0.f;

    const int r = tid >> 1;
    const int s = (tid & 1) * 4;
    const float* __restrict__ Arow = A + (size_t)(m0 + r) * Hh + kbeg + s;
    const float* __restrict__ Brow = Wr + (size_t)(tid >> 1) * Hh + kbeg + ((tid & 1) * 4);

    float4 a_n; float4 b_n = make_float4(0.f,0.f,0.f,0.f);

    a_n = *(const float4*)&Arow[0];
    if (tid < 64) b_n = *(const float4*)&Brow[0];
    As[0][s + 0][r] = a_n.x; As[0][s + 1][r] = a_n.y;
    As[0][s + 2][r] = a_n.z; As[0][s + 3][r] = a_n.w;
    if (tid < 64) {
        int bn = tid >> 1, bs = (tid & 1) * 4;
        Bs[0][bs + 0][bn] = b_n.x; Bs[0][bs + 1][bn] = b_n.y;
        Bs[0][bs + 2][bn] = b_n.z; Bs[0][bs + 3][bn] = b_n.w;
    }
    __syncthreads();

    int buf = 0;
    const int KC = Hh / KSPLIT;
    for (int k0 = 8; k0 <= KC; k0 += 8) {
        const bool more = (k0 < KC);
        if (more) {
            a_n = *(const float4*)&Arow[k0];
            if (tid < 64) b_n = *(const float4*)&Brow[k0];
        }

        #pragma unroll
        for (int k = 0; k < 8; k++) {
            float4 a0 = *(const float4*)&As[buf][k][ty * 4];
            float4 b0 = *(const float4*)&Bs[buf][k][tx * 4];
            float av[4] = {a0.x, a0.y, a0.z, a0.w};
            float bv[4] = {b0.x, b0.y, b0.z, b0.w};
            #pragma unroll
            for (int ii = 0; ii < 4; ii++)
                #pragma unroll
                for (int jj = 0; jj < 4; jj++)
                    acc[ii][jj] += av[ii] * bv[jj];
        }

        if (more) {
            int nb = buf ^ 1;
            As[nb][s + 0][r] = a_n.x; As[nb][s + 1][r] = a_n.y;
            As[nb][s + 2][r] = a_n.z; As[nb][s + 3][r] = a_n.w;
            if (tid < 64) {
                int bn = tid >> 1, bs = (tid & 1) * 4;
                Bs[nb][bs + 0][bn] = b_n.x; Bs[nb][bs + 1][bn] = b_n.y;
                Bs[nb][bs + 2][bn] = b_n.z; Bs[nb][bs + 3][bn] = b_n.w;
            }
            buf = nb;
            __syncthreads();
        }
    }

    float* __restrict__ part = (float*)g_fc3p + (size_t)ks * Pp * Rr;
    #pragma unroll
    for (int ii = 0; ii < 4; ii++) {
        int m = m0 + ty * 4 + ii;
        #pragma unroll
        for (int jj = 0; jj < 4; jj++) {
            int nn = tx * 4 + jj;
            part[(size_t)m * Rr + nn] = acc[ii][jj];
        }
    }
}

__global__ void fc3_reduce_kernel(const float* __restrict__ br,
                                  float* __restrict__ out)
{
    int i = blockIdx.x * blockDim.x + threadIdx.x;
    if (i < Pp * Rr) {
        const float* p = (const float*)g_fc3p;
        float v = p[i] + p[i + Pp*Rr] + p[i + 2*Pp*Rr] + p[i + 3*Pp*Rr];
        out[i] = v + br[i & (Rr - 1)];
    }
}

// ---------------------------------------------------------------------------
__global__ void pack_kernel(const float* __restrict__ trig,
                            const int* __restrict__ labels,
                            float* __restrict__ out, int out_size)
{
    int i = blockIdx.x * blockDim.x + threadIdx.x;
    const int PR = Pp * Rr;
    const int BT = Bb * Tt;
    if (out_size >= PR + BT && i < BT)        out[PR + i]      = trig[i];
    if (out_size >= PR + BT + Pp && i < Pp)   out[PR + BT + i] = (float)labels[i];
}

// ---------------------------------------------------------------------------
extern "C" void kernel_launch(void* const* d_in, const int* in_sizes, int n_in,
                              void* d_out, int out_size)
{
    const float* x     = (const float*)d_in[0];
    const float* trig  = (const float*)d_in[1];
    const int*   bidx  = (const int*)  d_in[2];
    const int*   hidx  = (const int*)  d_in[3];
    const int*   hspan = (const int*)  d_in[4];
    const int*   tidx  = (const int*)  d_in[5];
    const int*   tspan = (const int*)  d_in[6];
    const int*   labels= (const int*)  d_in[7];
    const float* c1w   = (const float*)d_in[8];
    const float* c1b   = (const float*)d_in[9];
    const float* c2w   = (const float*)d_in[10];
    const float* c2b   = (const float*)d_in[11];
    const float* w1    = (const float*)d_in[12];
    const float* b1    = (const float*)d_in[13];
    const float* w2    = (const float*)d_in[14];
    const float* b2    = (const float*)d_in[15];
    const float* wr    = (const float*)d_in[16];
    const float* br    = (const float*)d_in[17];
    float* out = (float*)d_out;

    float *pmaxed, *ph1, *ph2;
    cudaGetSymbolAddress((void**)&pmaxed, g_maxed);
    cudaGetSymbolAddress((void**)&ph1,    g_h1);
    cudaGetSymbolAddress((void**)&ph2,    g_h2);

    // Conv block 1: (B,E,T) -> g_x1 (B,E,T)
    {
        dim3 grid((Bb * Tt) / 128, Ee / 128);
        conv_block_kernel<0><<<grid, 256>>>(x, c1w, c1b);
    }
    // Conv block 2: g_x1 -> g_xbte (B,T,E)
    {
        dim3 grid((Bb * Tt) / 128, Ee / 128);
        conv_block_kernel<1><<<grid, 256>>>(nullptr, c2w, c2b);
    }
    // Span max gather
    span_kernel<<<Pp, 128>>>(bidx, hidx, hspan, tidx, tspan);

    // FC1: (P,512) x (1024,512)^T -> (P,1024), relu
    {
        dim3 grid(Hh / 128, Pp / 128);
        gemm_nt_kernel<true><<<grid, 256>>>(pmaxed, w1, b1, ph1, Pp, Hh, Ee);
    }
    // FC2: (P,1024) x (1024,1024)^T -> (P,1024), relu
    {
        dim3 grid(Hh / 128, Pp / 128);
        gemm_nt_kernel<true><<<grid, 256>>>(ph1, w2, b2, ph2, Pp, Hh, Hh);
    }
    // FC3: split-K over 4 chunks, then reduce+bias into d_out
    {
        dim3 grid(KSPLIT, Pp / 128);
        fc3_splitk_kernel<<<grid, 256>>>(ph2, wr);
        fc3_reduce_kernel<<<(Pp * Rr + 255) / 256, 256>>>(br, out);
    }
    // trig_attn + rel_labels passthrough
    pack_kernel<<<(8192 + 255) / 256, 256>>>(trig, labels, out, out_size);
}

// round 7
// speedup vs baseline: 1.7673x; 1.2855x over previous
#include <cuda_runtime.h>
#include <cuda_bf16.h>
#include <math.h>
#include <stdint.h>

// Problem constants
#define Bb 16
#define Ee 512
#define Tt 512
#define Hh 1024
#define Rr 32
#define Pp 8192
#define Ww 3
#define KCONV (Ee*Ww)   // 1536
#define KSPLIT 4

typedef unsigned long long u64;

// Packed f32x2 helpers (conv kernels keep the R5 FFMA2 path)
#define FMA2(d, a, b) \
    asm("fma.rn.f32x2 %0, %1, %2, %0;" : "+l"(d) : "l"(a), "l"(b))
#define DUP2(d, s) \
    asm("mov.b64 %0, {%1, %1};" : "=l"(d) : "f"(s))
#define UNPK2(lo, hi, v) \
    asm("mov.b64 {%0, %1}, %2;" : "=f"(lo), "=f"(hi) : "l"(v))

// bf16 m16n8k16 tensor-core MMA (baseline PTX, valid on sm_103)
#define MMA16816(C, A, B) \
    asm volatile("mma.sync.aligned.m16n8k16.row.col.f32.bf16.bf16.f32 " \
        "{%0,%1,%2,%3}, {%4,%5,%6,%7}, {%8,%9}, {%0,%1,%2,%3};" \
        : "+f"((C)[0]), "+f"((C)[1]), "+f"((C)[2]), "+f"((C)[3]) \
        : "r"((A)[0]), "r"((A)[1]), "r"((A)[2]), "r"((A)[3]), \
          "r"((B)[0]), "r"((B)[1]))

__device__ __forceinline__ uint32_t smem_u32(const void* p) {
    uint32_t a;
    asm("{ .reg .u64 t; cvta.to.shared.u64 t, %1; cvt.u32.u64 %0, t; }" : "=r"(a) : "l"(p));
    return a;
}

// Scratch (device globals: allocation-free per harness rules)
__device__ float g_x1[Bb*Ee*Tt];
__device__ float g_xbte[Bb*Tt*Ee];
__device__ __nv_bfloat16 g_mx_h[Pp*Ee];
__device__ __nv_bfloat16 g_mx_l[Pp*Ee];
__device__ __nv_bfloat16 g_w1h[Hh*Ee];
__device__ __nv_bfloat16 g_w1l[Hh*Ee];
__device__ __nv_bfloat16 g_w2h[Hh*Hh];
__device__ __nv_bfloat16 g_w2l[Hh*Hh];
__device__ __nv_bfloat16 g_h1h[Pp*Hh];
__device__ __nv_bfloat16 g_h1l[Pp*Hh];
__device__ float g_h2[Pp*Hh];
__device__ float g_fc3p[KSPLIT*Pp*Rr];

// ---------------------------------------------------------------------------
// Residual conv block (unchanged from round 5: halo-tile 3-tap, FFMA2)
// ---------------------------------------------------------------------------
template<int MODE>
__global__ __launch_bounds__(256, 2) void conv_block_kernel(
    const float* __restrict__ xin_param,
    const float* __restrict__ w,
    const float* __restrict__ bias)
{
    const float* __restrict__ xin = (MODE == 0) ? xin_param : (const float*)g_x1;
    float* __restrict__ out       = (MODE == 0) ? (float*)g_x1 : (float*)g_xbte;

    __shared__ __align__(16) float Xs[2][8][136];
    __shared__ __align__(16) float Ws[2][24*128];

    const int tid = threadIdx.x;
    const int n0 = blockIdx.x * 128;
    const int m0 = blockIdx.y * 128;
    const int b  = n0 >> 9;
    const int t0 = n0 & 511;
    const int tx = tid & 15;
    const int ty = tid >> 4;

    u64 acc2[4][8];
    #pragma unroll
    for (int i = 0; i < 4; i++)
        #pragma unroll
        for (int j = 0; j < 8; j++) acc2[i][j] = 0ULL;

    const int xrow = tid >> 5;
    const int lane = tid & 31;
    const bool lval = (t0 > 0);
    const bool rval = (t0 + 128 < Tt);
    const float* __restrict__ xrow_base0 = xin + ((size_t)b * Ee + xrow) * Tt + t0;

    int wm[3], wq4[3];
    #pragma unroll
    for (int j = 0; j < 3; j++) {
        int f4idx = tid + 256 * j;
        wm[j]  = f4idx / 6;
        wq4[j] = (f4idx % 6) * 4;
    }
    const float* __restrict__ wbase0 = w + (size_t)m0 * KCONV;

    float4 xr; float xh0 = 0.f, xh1 = 0.f;
    float4 wr4[3];

    {
        const float* xr0 = xrow_base0;
        xr = *(const float4*)&xr0[lane * 4];
        if (lane == 0) xh0 = lval ? xr0[-1]  : 0.f;
        if (lane == 1) xh1 = rval ? xr0[128] : 0.f;
        #pragma unroll
        for (int j = 0; j < 3; j++)
            wr4[j] = *(const float4*)&wbase0[(size_t)wm[j] * KCONV + wq4[j]];

        Xs[0][xrow][4 + lane * 4 + 0] = xr.x;
        Xs[0][xrow][4 + lane * 4 + 1] = xr.y;
        Xs[0][xrow][4 + lane * 4 + 2] = xr.z;
        Xs[0][xrow][4 + lane * 4 + 3] = xr.w;
        if (lane == 0) Xs[0][xrow][3]   = xh0;
        if (lane == 1) Xs[0][xrow][132] = xh1;
        #pragma unroll
        for (int j = 0; j < 3; j++) {
            Ws[0][(wq4[j] + 0) * 128 + wm[j]] = wr4[j].x;
            Ws[0][(wq4[j] + 1) * 128 + wm[j]] = wr4[j].y;
            Ws[0][(wq4[j] + 2) * 128 + wm[j]] = wr4[j].z;
            Ws[0][(wq4[j] + 3) * 128 + wm[j]] = wr4[j].w;
        }
    }
    __syncthreads();

    int buf = 0;
    for (int ei0 = 8; ei0 <= Ee; ei0 += 8) {
        const bool more = (ei0 < Ee);
        if (more) {
            const float* xr0 = xrow_base0 + (size_t)ei0 * Tt;
            xr = *(const float4*)&xr0[lane * 4];
            if (lane == 0) xh0 = lval ? xr0[-1]  : 0.f;
            if (lane == 1) xh1 = rval ? xr0[128] : 0.f;
            const float* wb = wbase0 + (size_t)ei0 * 3;
            #pragma unroll
            for (int j = 0; j < 3; j++)
                wr4[j] = *(const float4*)&wb[(size_t)wm[j] * KCONV + wq4[j]];
        }

        #pragma unroll
        for (int k = 0; k < 8; k++) {
            const float* xk = &Xs[buf][k][0];
            float4 p0 = *(const float4*)&xk[tx * 4];
            float4 q0 = *(const float4*)&xk[tx * 4 + 4];
            float  s0 = xk[tx * 4 + 8];
            float4 p1 = *(const float4*)&xk[tx * 4 + 64];
            float4 q1 = *(const float4*)&xk[tx * 4 + 68];
            float  s1 = xk[tx * 4 + 72];

            u64 w0d[6], w1d[6];
            DUP2(w0d[0], p0.w); DUP2(w0d[1], q0.x); DUP2(w0d[2], q0.y);
            DUP2(w0d[3], q0.z); DUP2(w0d[4], q0.w); DUP2(w0d[5], s0);
            DUP2(w1d[0], p1.w); DUP2(w1d[1], q1.x); DUP2(w1d[2], q1.y);
            DUP2(w1d[3], q1.z); DUP2(w1d[4], q1.w); DUP2(w1d[5], s1);

            #pragma unroll
            for (int dk = 0; dk < 3; dk++) {
                const float* wk = &Ws[buf][(k * 3 + dk) * 128];
                ulonglong2 A0 = *(const ulonglong2*)&wk[ty * 4];
                ulonglong2 A1 = *(const ulonglong2*)&wk[ty * 4 + 64];
                u64 av2[4] = {A0.x, A0.y, A1.x, A1.y};
                #pragma unroll
                for (int ii = 0; ii < 4; ii++) {
                    #pragma unroll
                    for (int jj = 0; jj < 4; jj++)
                        FMA2(acc2[ii][jj],     av2[ii], w0d[dk + jj]);
                    #pragma unroll
                    for (int jj = 0; jj < 4; jj++)
                        FMA2(acc2[ii][jj + 4], av2[ii], w1d[dk + jj]);
                }
            }
        }

        if (more) {
            const int nb = buf ^ 1;
            Xs[nb][xrow][4 + lane * 4 + 0] = xr.x;
            Xs[nb][xrow][4 + lane * 4 + 1] = xr.y;
            Xs[nb][xrow][4 + lane * 4 + 2] = xr.z;
            Xs[nb][xrow][4 + lane * 4 + 3] = xr.w;
            if (lane == 0) Xs[nb][xrow][3]   = xh0;
            if (lane == 1) Xs[nb][xrow][132] = xh1;
            #pragma unroll
            for (int j = 0; j < 3; j++) {
                Ws[nb][(wq4[j] + 0) * 128 + wm[j]] = wr4[j].x;
                Ws[nb][(wq4[j] + 1) * 128 + wm[j]] = wr4[j].y;
                Ws[nb][(wq4[j] + 2) * 128 + wm[j]] = wr4[j].z;
                Ws[nb][(wq4[j] + 3) * 128 + wm[j]] = wr4[j].w;
            }
            buf = nb;
            __syncthreads();
        }
    }

    #pragma unroll
    for (int ii = 0; ii < 4; ii++) {
        int m = m0 + ((ii < 2) ? ty * 4 + ii * 2 : 64 + ty * 4 + (ii - 2) * 2);
        float blo = bias[m], bhi = bias[m + 1];
        #pragma unroll
        for (int jj = 0; jj < 8; jj++) {
            int t2 = t0 + tx * 4 + ((jj < 4) ? jj : (64 + jj - 4));
            float lo, hi;
            UNPK2(lo, hi, acc2[ii][jj]);
            float rlo = xin[((size_t)b * Ee + m)     * Tt + t2];
            float rhi = xin[((size_t)b * Ee + m + 1) * Tt + t2];
            float vlo = lo + blo; vlo = (vlo > 0.f ? vlo : 0.f) + rlo;
            float vhi = hi + bhi; vhi = (vhi > 0.f ? vhi : 0.f) + rhi;
            if (MODE == 0) {
                out[((size_t)b * Ee + m)     * Tt + t2] = vlo;
                out[((size_t)b * Ee + m + 1) * Tt + t2] = vhi;
            } else {
                out[((size_t)b * Tt + t2) * Ee + m]     = vlo;
                out[((size_t)b * Tt + t2) * Ee + m + 1] = vhi;
            }
        }
    }
}

// ---------------------------------------------------------------------------
// Span max gather -> bf16 hi/lo split output (feeds tensor-core FC1)
// ---------------------------------------------------------------------------
__global__ __launch_bounds__(128) void span_kernel(
    const int* __restrict__ bidx,
    const int* __restrict__ hidx, const int* __restrict__ hspan,
    const int* __restrict__ tidx, const int* __restrict__ tspan)
{
    const int p  = blockIdx.x;
    const int e4 = threadIdx.x;
    const int b  = bidx[p];
    const float4* __restrict__ base = (const float4*)g_xbte + (size_t)b * Tt * (Ee / 4);

    const int h0 = hidx[p], hs = hspan[p];
    const int t0 = tidx[p], ts = tspan[p];

    float4 hm = make_float4(-INFINITY, -INFINITY, -INFINITY, -INFINITY);
    for (int s = 0; s < hs; s++) {
        float4 v = base[(size_t)(h0 + s) * (Ee / 4) + e4];
        hm.x = fmaxf(hm.x, v.x); hm.y = fmaxf(hm.y, v.y);
        hm.z = fmaxf(hm.z, v.z); hm.w = fmaxf(hm.w, v.w);
    }
    float4 tm = make_float4(-INFINITY, -INFINITY, -INFINITY, -INFINITY);
    for (int s = 0; s < ts; s++) {
        float4 v = base[(size_t)(t0 + s) * (Ee / 4) + e4];
        tm.x = fmaxf(tm.x, v.x); tm.y = fmaxf(tm.y, v.y);
        tm.z = fmaxf(tm.z, v.z); tm.w = fmaxf(tm.w, v.w);
    }
    float o[4] = {hm.x + tm.x, hm.y + tm.y, hm.z + tm.z, hm.w + tm.w};

    size_t off = (size_t)p * Ee + e4 * 4;
    #pragma unroll
    for (int j = 0; j < 4; j++) {
        __nv_bfloat16 h = __float2bfloat16(o[j]);
        __nv_bfloat16 l = __float2bfloat16(o[j] - __bfloat162float(h));
        g_mx_h[off + j] = h;
        g_mx_l[off + j] = l;
    }
}

// fp32 -> bf16 hi/lo conversion (weights)
__global__ void cvt_hilo_kernel(const float* __restrict__ in,
                                __nv_bfloat16* __restrict__ hi,
                                __nv_bfloat16* __restrict__ lo, int n)
{
    int i = blockIdx.x * blockDim.x + threadIdx.x;
    if (i < n) {
        float x = in[i];
        __nv_bfloat16 h = __float2bfloat16(x);
        hi[i] = h;
        lo[i] = __float2bfloat16(x - __bfloat162float(h));
    }
}

// ---------------------------------------------------------------------------
// Tensor-core bf16x3 NT GEMM via mma.sync.m16n8k16:
//   C[m][n] = relu( sum_k A[m][k]*B[n][k] + bias[n] ),  A=Ah+Al, B=Bh+Bl,
//   D = Ah*Bh + Ah*Bl + Al*Bh, fp32 accumulate in registers.
// Block 128x128, 8 warps (2M x 4N), warp tile 64x32.
// cp.async double-buffered K-chunks of 32; smem rows stride 40 bf16 (80B,
// conflict-free fragment LDS: 20-bank row stride).
// HILO: write bf16 hi/lo pair; else fp32.
// ---------------------------------------------------------------------------
#define SROW 40
#define SEC_ELEMS (128*SROW)
#define SEC_BYTES (SEC_ELEMS*2)
#define BUF_BYTES (4*SEC_BYTES)      // 40960
#define FC_SMEM   (2*BUF_BYTES)      // 81920

template<bool HILO>
__global__ __launch_bounds__(256, 1) void fc_mma_kernel(
    const __nv_bfloat16* __restrict__ Ah, const __nv_bfloat16* __restrict__ Al,
    const __nv_bfloat16* __restrict__ Bh, const __nv_bfloat16* __restrict__ Bl,
    const float* __restrict__ bias, int K, int N,
    float* __restrict__ Cf,
    __nv_bfloat16* __restrict__ Ch, __nv_bfloat16* __restrict__ Cl)
{
    extern __shared__ __align__(16) unsigned char SM[];

    const int tid  = threadIdx.x;
    const int wid  = tid >> 5;
    const int lane = tid & 31;
    const int g    = lane >> 2;     // fragment group (row / n-col)
    const int t    = lane & 3;      // fragment thread-in-group
    const int n0   = blockIdx.x * 128;
    const int m0   = blockIdx.y * 128;
    const int wm   = wid & 1;       // 0..1 (64 M rows each)
    const int wn   = wid >> 1;      // 0..3 (32 N cols each)
    const uint32_t smbase = smem_u32(SM);

    float acc[4][4][4];
    #pragma unroll
    for (int i = 0; i < 4; i++)
        #pragma unroll
        for (int j = 0; j < 4; j++)
            #pragma unroll
            for (int q = 0; q < 4; q++) acc[i][j][q] = 0.f;

    // ---- async chunk loader: 4 sections x 128 rows x 32 bf16 -> smem ----
    auto issue_chunk = [&](int kbeg, int bsel) {
        uint32_t base = smbase + bsel * BUF_BYTES;
        #pragma unroll
        for (int i = 0; i < 8; i++) {
            int idx = tid + 256 * i;          // 0..2047
            int sec = idx >> 9;               // 0..3
            int rem = idx & 511;
            int row = rem >> 2;               // 0..127
            int q   = rem & 3;                // 16B unit in 64B row
            const __nv_bfloat16* gsrc;
            if (sec == 0)      gsrc = Ah + (size_t)(m0 + row) * K + kbeg + q * 8;
            else if (sec == 1) gsrc = Al + (size_t)(m0 + row) * K + kbeg + q * 8;
            else if (sec == 2) gsrc = Bh + (size_t)(n0 + row) * K + kbeg + q * 8;
            else               gsrc = Bl + (size_t)(n0 + row) * K + kbeg + q * 8;
            uint32_t daddr = base + sec * SEC_BYTES + row * (SROW * 2) + q * 16;
            asm volatile("cp.async.cg.shared.global [%0], [%1], 16;"
                         :: "r"(daddr), "l"(gsrc));
        }
        asm volatile("cp.async.commit_group;" ::: "memory");
    };

    // ---- compute one K=32 chunk from smem buffer bsel ----
    auto compute_chunk = [&](int bsel) {
        const __nv_bfloat16* sAh = (const __nv_bfloat16*)(SM + bsel * BUF_BYTES);
        const __nv_bfloat16* sAl = sAh + SEC_ELEMS;
        const __nv_bfloat16* sBh = sAl + SEC_ELEMS;
        const __nv_bfloat16* sBl = sBh + SEC_ELEMS;

        #pragma unroll
        for (int ko = 0; ko < 32; ko += 16) {
            uint32_t ah[4][4], al[4][4], bh[4][2], bl[4][2];
            #pragma unroll
            for (int mt = 0; mt < 4; mt++) {
                const __nv_bfloat16* r = sAh + (wm * 64 + mt * 16 + g) * SROW + ko + t * 2;
                ah[mt][0] = *(const uint32_t*)r;
                ah[mt][1] = *(const uint32_t*)(r + 8 * SROW);
                ah[mt][2] = *(const uint32_t*)(r + 8);
                ah[mt][3] = *(const uint32_t*)(r + 8 * SROW + 8);
                const __nv_bfloat16* r2 = sAl + (wm * 64 + mt * 16 + g) * SROW + ko + t * 2;
                al[mt][0] = *(const uint32_t*)r2;
                al[mt][1] = *(const uint32_t*)(r2 + 8 * SROW);
                al[mt][2] = *(const uint32_t*)(r2 + 8);
                al[mt][3] = *(const uint32_t*)(r2 + 8 * SROW + 8);
            }
            #pragma unroll
            for (int nt = 0; nt < 4; nt++) {
                const __nv_bfloat16* r = sBh + (wn * 32 + nt * 8 + g) * SROW + ko + t * 2;
                bh[nt][0] = *(const uint32_t*)r;
                bh[nt][1] = *(const uint32_t*)(r + 8);
                const __nv_bfloat16* r2 = sBl + (wn * 32 + nt * 8 + g) * SROW + ko + t * 2;
                bl[nt][0] = *(const uint32_t*)r2;
                bl[nt][1] = *(const uint32_t*)(r2 + 8);
            }
            #pragma unroll
            for (int mt = 0; mt < 4; mt++)
                #pragma unroll
                for (int nt = 0; nt < 4; nt++)
                    MMA16816(acc[mt][nt], ah[mt], bh[nt]);
            #pragma unroll
            for (int mt = 0; mt < 4; mt++)
                #pragma unroll
                for (int nt = 0; nt < 4; nt++)
                    MMA16816(acc[mt][nt], ah[mt], bl[nt]);
            #pragma unroll
            for (int mt = 0; mt < 4; mt++)
                #pragma unroll
                for (int nt = 0; nt < 4; nt++)
                    MMA16816(acc[mt][nt], al[mt], bh[nt]);
        }
    };

    const int NC = K / 32;
    issue_chunk(0, 0);
    for (int c = 0; c < NC; c++) {
        if (c + 1 < NC) {
            issue_chunk((c + 1) * 32, (c + 1) & 1);
            asm volatile("cp.async.wait_group 1;" ::: "memory");
        } else {
            asm volatile("cp.async.wait_group 0;" ::: "memory");
        }
        __syncthreads();
        compute_chunk(c & 1);
        __syncthreads();
    }

    // ---- epilogue: bias + relu ----
    #pragma unroll
    for (int mt = 0; mt < 4; mt++) {
        const int m = m0 + wm * 64 + mt * 16 + g;
        #pragma unroll
        for (int nt = 0; nt < 4; nt++) {
            const int n = n0 + wn * 32 + nt * 8 + t * 2;
            float b0 = bias[n], b1 = bias[n + 1];
            float v00 = acc[mt][nt][0] + b0;  // row m,   col n
            float v01 = acc[mt][nt][1] + b1;  // row m,   col n+1
            float v10 = acc[mt][nt][2] + b0;  // row m+8, col n
            float v11 = acc[mt][nt][3] + b1;  // row m+8, col n+1
            v00 = (v00 > 0.f) ? v00 : 0.f;
            v01 = (v01 > 0.f) ? v01 : 0.f;
            v10 = (v10 > 0.f) ? v10 : 0.f;
            v11 = (v11 > 0.f) ? v11 : 0.f;
            if (HILO) {
                __nv_bfloat16 h00 = __float2bfloat16(v00);
                __nv_bfloat16 h01 = __float2bfloat16(v01);
                __nv_bfloat16 h10 = __float2bfloat16(v10);
                __nv_bfloat16 h11 = __float2bfloat16(v11);
                __nv_bfloat162 hp0; hp0.x = h00; hp0.y = h01;
                __nv_bfloat162 hp1; hp1.x = h10; hp1.y = h11;
                __nv_bfloat162 lp0;
                lp0.x = __float2bfloat16(v00 - __bfloat162float(h00));
                lp0.y = __float2bfloat16(v01 - __bfloat162float(h01));
                __nv_bfloat162 lp1;
                lp1.x = __float2bfloat16(v10 - __bfloat162float(h10));
                lp1.y = __float2bfloat16(v11 - __bfloat162float(h11));
                *(__nv_bfloat162*)(Ch + (size_t)m * N + n)       = hp0;
                *(__nv_bfloat162*)(Cl + (size_t)m * N + n)       = lp0;
                *(__nv_bfloat162*)(Ch + (size_t)(m + 8) * N + n) = hp1;
                *(__nv_bfloat162*)(Cl + (size_t)(m + 8) * N + n) = lp1;
            } else {
                float2 f0 = make_float2(v00, v01);
                float2 f1 = make_float2(v10, v11);
                *(float2*)(Cf + (size_t)m * N + n)       = f0;
                *(float2*)(Cf + (size_t)(m + 8) * N + n) = f1;
            }
        }
    }
}

// ---------------------------------------------------------------------------
// FC3 split-K GEMM (scalar; unchanged) + reduce
// ---------------------------------------------------------------------------
__global__ __launch_bounds__(256, 2) void fc3_splitk_kernel(
    const float* __restrict__ A,
    const float* __restrict__ Wr)
{
    __shared__ float As[2][8][128];
    __shared__ float Bs[2][8][32];

    const int tid = threadIdx.x;
    const int ks  = blockIdx.x;
    const int m0  = blockIdx.y * 128;
    const int kbeg = ks * (Hh / KSPLIT);
    const int tx = tid & 7;
    const int ty = tid >> 3;

    float acc[4][4];
    #pragma unroll
    for (int i = 0; i < 4; i++)
        #pragma unroll
        for (int j = 0; j < 4; j++) acc[i][j] = 0.f;

    const int r = tid >> 1;
    const int s = (tid & 1) * 4;
    const float* __restrict__ Arow = A + (size_t)(m0 + r) * Hh + kbeg + s;
    const float* __restrict__ Brow = Wr + (size_t)(tid >> 1) * Hh + kbeg + ((tid & 1) * 4);

    float4 a_n; float4 b_n = make_float4(0.f,0.f,0.f,0.f);

    a_n = *(const float4*)&Arow[0];
    if (tid < 64) b_n = *(const float4*)&Brow[0];
    As[0][s + 0][r] = a_n.x; As[0][s + 1][r] = a_n.y;
    As[0][s + 2][r] = a_n.z; As[0][s + 3][r] = a_n.w;
    if (tid < 64) {
        int bn = tid >> 1, bs = (tid & 1) * 4;
        Bs[0][bs + 0][bn] = b_n.x; Bs[0][bs + 1][bn] = b_n.y;
        Bs[0][bs + 2][bn] = b_n.z; Bs[0][bs + 3][bn] = b_n.w;
    }
    __syncthreads();

    int buf = 0;
    const int KC = Hh / KSPLIT;
    for (int k0 = 8; k0 <= KC; k0 += 8) {
        const bool more = (k0 < KC);
        if (more) {
            a_n = *(const float4*)&Arow[k0];
            if (tid < 64) b_n = *(const float4*)&Brow[k0];
        }

        #pragma unroll
        for (int k = 0; k < 8; k++) {
            float4 a0 = *(const float4*)&As[buf][k][ty * 4];
            float4 b0 = *(const float4*)&Bs[buf][k][tx * 4];
            float av[4] = {a0.x, a0.y, a0.z, a0.w};
            float bv[4] = {b0.x, b0.y, b0.z, b0.w};
            #pragma unroll
            for (int ii = 0; ii < 4; ii++)
                #pragma unroll
                for (int jj = 0; jj < 4; jj++)
                    acc[ii][jj] += av[ii] * bv[jj];
        }

        if (more) {
            int nb = buf ^ 1;
            As[nb][s + 0][r] = a_n.x; As[nb][s + 1][r] = a_n.y;
            As[nb][s + 2][r] = a_n.z; As[nb][s + 3][r] = a_n.w;
            if (tid < 64) {
                int bn = tid >> 1, bs = (tid & 1) * 4;
                Bs[nb][bs + 0][bn] = b_n.x; Bs[nb][bs + 1][bn] = b_n.y;
                Bs[nb][bs + 2][bn] = b_n.z; Bs[nb][bs + 3][bn] = b_n.w;
            }
            buf = nb;
            __syncthreads();
        }
    }

    float* __restrict__ part = (float*)g_fc3p + (size_t)ks * Pp * Rr;
    #pragma unroll
    for (int ii = 0; ii < 4; ii++) {
        int m = m0 + ty * 4 + ii;
        #pragma unroll
        for (int jj = 0; jj < 4; jj++) {
            int nn = tx * 4 + jj;
            part[(size_t)m * Rr + nn] = acc[ii][jj];
        }
    }
}

__global__ void fc3_reduce_kernel(const float* __restrict__ br,
                                  float* __restrict__ out)
{
    int i = blockIdx.x * blockDim.x + threadIdx.x;
    if (i < Pp * Rr) {
        const float* p = (const float*)g_fc3p;
        float v = p[i] + p[i + Pp*Rr] + p[i + 2*Pp*Rr] + p[i + 3*Pp*Rr];
        out[i] = v + br[i & (Rr - 1)];
    }
}

// ---------------------------------------------------------------------------
__global__ void pack_kernel(const float* __restrict__ trig,
                            const int* __restrict__ labels,
                            float* __restrict__ out, int out_size)
{
    int i = blockIdx.x * blockDim.x + threadIdx.x;
    const int PR = Pp * Rr;
    const int BT = Bb * Tt;
    if (out_size >= PR + BT && i < BT)        out[PR + i]      = trig[i];
    if (out_size >= PR + BT + Pp && i < Pp)   out[PR + BT + i] = (float)labels[i];
}

// ---------------------------------------------------------------------------
extern "C" void kernel_launch(void* const* d_in, const int* in_sizes, int n_in,
                              void* d_out, int out_size)
{
    const float* x     = (const float*)d_in[0];
    const float* trig  = (const float*)d_in[1];
    const int*   bidx  = (const int*)  d_in[2];
    const int*   hidx  = (const int*)  d_in[3];
    const int*   hspan = (const int*)  d_in[4];
    const int*   tidx  = (const int*)  d_in[5];
    const int*   tspan = (const int*)  d_in[6];
    const int*   labels= (const int*)  d_in[7];
    const float* c1w   = (const float*)d_in[8];
    const float* c1b   = (const float*)d_in[9];
    const float* c2w   = (const float*)d_in[10];
    const float* c2b   = (const float*)d_in[11];
    const float* w1    = (const float*)d_in[12];
    const float* b1    = (const float*)d_in[13];
    const float* w2    = (const float*)d_in[14];
    const float* b2    = (const float*)d_in[15];
    const float* wr    = (const float*)d_in[16];
    const float* br    = (const float*)d_in[17];
    float* out = (float*)d_out;

    __nv_bfloat16 *pmxh, *pmxl, *pw1h, *pw1l, *pw2h, *pw2l, *ph1h, *ph1l;
    float *ph2;
    cudaGetSymbolAddress((void**)&pmxh, g_mx_h);
    cudaGetSymbolAddress((void**)&pmxl, g_mx_l);
    cudaGetSymbolAddress((void**)&pw1h, g_w1h);
    cudaGetSymbolAddress((void**)&pw1l, g_w1l);
    cudaGetSymbolAddress((void**)&pw2h, g_w2h);
    cudaGetSymbolAddress((void**)&pw2l, g_w2l);
    cudaGetSymbolAddress((void**)&ph1h, g_h1h);
    cudaGetSymbolAddress((void**)&ph1l, g_h1l);
    cudaGetSymbolAddress((void**)&ph2,  g_h2);

    static int smem_set = 0;
    if (!smem_set) {
        cudaFuncSetAttribute(fc_mma_kernel<true>,
                             cudaFuncAttributeMaxDynamicSharedMemorySize, FC_SMEM);
        cudaFuncSetAttribute(fc_mma_kernel<false>,
                             cudaFuncAttributeMaxDynamicSharedMemorySize, FC_SMEM);
        smem_set = 1;
    }

    // Conv blocks (CUDA cores, unchanged)
    {
        dim3 grid((Bb * Tt) / 128, Ee / 128);
        conv_block_kernel<0><<<grid, 256>>>(x, c1w, c1b);
        conv_block_kernel<1><<<grid, 256>>>(nullptr, c2w, c2b);
    }
    // Weight conversions
    cvt_hilo_kernel<<<(Hh*Ee + 255)/256, 256>>>(w1, pw1h, pw1l, Hh*Ee);
    cvt_hilo_kernel<<<(Hh*Hh + 255)/256, 256>>>(w2, pw2h, pw2l, Hh*Hh);

    // Span max -> bf16 hi/lo
    span_kernel<<<Pp, 128>>>(bidx, hidx, hspan, tidx, tspan);

    // FC1 (mma.sync bf16x3): (P,512)x(1024,512)^T -> h1 hi/lo, relu
    {
        dim3 grid(Hh / 128, Pp / 128);
        fc_mma_kernel<true><<<grid, 256, FC_SMEM>>>(
            pmxh, pmxl, pw1h, pw1l, b1, Ee, Hh, nullptr, ph1h, ph1l);
    }
    // FC2 (mma.sync bf16x3): (P,1024)x(1024,1024)^T -> h2 fp32, relu
    {
        dim3 grid(Hh / 128, Pp / 128);
        fc_mma_kernel<false><<<grid, 256, FC_SMEM>>>(
            ph1h, ph1l, pw2h, pw2l, b2, Hh, Hh, ph2, nullptr, nullptr);
    }
    // FC3: split-K + reduce into d_out
    {
        dim3 grid(KSPLIT, Pp / 128);
        fc3_splitk_kernel<<<grid, 256>>>(ph2, wr);
        fc3_reduce_kernel<<<(Pp * Rr + 255) / 256, 256>>>(br, out);
    }
    // trig_attn + rel_labels passthrough
    pack_kernel<<<(8192 + 255) / 256, 256>>>(trig, labels, out, out_size);
}

// round 9
// speedup vs baseline: 2.3043x; 1.3038x over previous
#include <cuda_runtime.h>
#include <cuda_bf16.h>
#include <math.h>
#include <stdint.h>

// Problem constants
#define Bb 16
#define Ee 512
#define Tt 512
#define Hh 1024
#define Rr 32
#define Pp 8192
#define Ww 3
#define KSPLIT 4

// bf16 m16n8k16 tensor-core MMA (baseline PTX, valid on sm_103)
#define MMA16816(C, A, B) \
    asm volatile("mma.sync.aligned.m16n8k16.row.col.f32.bf16.bf16.f32 " \
        "{%0,%1,%2,%3}, {%4,%5,%6,%7}, {%8,%9}, {%0,%1,%2,%3};" \
        : "+f"((C)[0]), "+f"((C)[1]), "+f"((C)[2]), "+f"((C)[3]) \
        : "r"((A)[0]), "r"((A)[1]), "r"((A)[2]), "r"((A)[3]), \
          "r"((B)[0]), "r"((B)[1]))

__device__ __forceinline__ uint32_t smem_u32(const void* p) {
    uint32_t a;
    asm("{ .reg .u64 t; cvta.to.shared.u64 t, %1; cvt.u32.u64 %0, t; }" : "=r"(a) : "l"(p));
    return a;
}

// Scratch (device globals: allocation-free per harness rules)
__device__ float g_x1[Bb*Ee*Tt];                 // conv1 out fp32 (B,E,T)
__device__ float g_xbte[Bb*Tt*Ee];               // conv2 out fp32 (B,T,E)
__device__ __nv_bfloat16 g_xh[Bb*Ee*Tt];         // input x hi/lo (B,E,T)
__device__ __nv_bfloat16 g_xl[Bb*Ee*Tt];
__device__ __nv_bfloat16 g_x1h[Bb*Ee*Tt];        // conv1 out hi/lo (B,E,T)
__device__ __nv_bfloat16 g_x1l[Bb*Ee*Tt];
__device__ __nv_bfloat16 g_wt1h[3*Ee*Ee];        // conv weights [dk][eo][ei]
__device__ __nv_bfloat16 g_wt1l[3*Ee*Ee];
__device__ __nv_bfloat16 g_wt2h[3*Ee*Ee];
__device__ __nv_bfloat16 g_wt2l[3*Ee*Ee];
__device__ __nv_bfloat16 g_mx_h[Pp*Ee];
__device__ __nv_bfloat16 g_mx_l[Pp*Ee];
__device__ __nv_bfloat16 g_w1h[Hh*Ee];
__device__ __nv_bfloat16 g_w1l[Hh*Ee];
__device__ __nv_bfloat16 g_w2h[Hh*Hh];
__device__ __nv_bfloat16 g_w2l[Hh*Hh];
__device__ __nv_bfloat16 g_h1h[Pp*Hh];
__device__ __nv_bfloat16 g_h1l[Pp*Hh];
__device__ float g_h2[Pp*Hh];
__device__ float g_fc3p[KSPLIT*Pp*Rr];

// fp32 -> bf16 hi/lo (elementwise)
__global__ void cvt_hilo_kernel(const float* __restrict__ in,
                                __nv_bfloat16* __restrict__ hi,
                                __nv_bfloat16* __restrict__ lo, int n)
{
    int i = blockIdx.x * blockDim.x + threadIdx.x;
    if (i < n) {
        float x = in[i];
        __nv_bfloat16 h = __float2bfloat16(x);
        hi[i] = h;
        lo[i] = __float2bfloat16(x - __bfloat162float(h));
    }
}

// conv weights (eo,ei,dk) -> transposed [dk][eo][ei] hi/lo
__global__ void cvt_wt_kernel(const float* __restrict__ w,
                              __nv_bfloat16* __restrict__ th,
                              __nv_bfloat16* __restrict__ tl)
{
    int i = blockIdx.x * blockDim.x + threadIdx.x;
    if (i < Ee * Ee * 3) {
        int eo  = i / (Ee * 3);
        int rem = i - eo * (Ee * 3);
        int ei  = rem / 3;
        int dk  = rem - ei * 3;
        float x = w[i];
        __nv_bfloat16 h = __float2bfloat16(x);
        int o = dk * (Ee * Ee) + eo * Ee + ei;
        th[o] = h;
        tl[o] = __float2bfloat16(x - __bfloat162float(h));
    }
}

// ---------------------------------------------------------------------------
// Conv residual block via mma.sync bf16x3:
//   y[b][eo][t] = relu( sum_dk sum_ei wt[dk][eo][ei]*x[b][ei][t+dk-1] + bias[eo] )
//                 + resid[b][eo][t]
// Block: 128 eo x 128 t, 8 warps (2M x 4N), warp tile 64x32.
// K-chunks of 32 ei, NC=16, double-buffered. A via cp.async (3 taps x 128 x 32),
// B via transposed LDG->STS scatter into [t_local 0..129][ei] rows (halo +-1).
// MODE 0: write g_x1 fp32 + g_x1h/l bf16 (B,E,T)
// MODE 1: write g_xbte fp32 (B,T,E)
// ---------------------------------------------------------------------------
#define CROWB 80                      // smem row bytes (40 bf16)
#define CAH 0
#define CAL (384*CROWB)               // 30720
#define CBH (2*384*CROWB)             // 61440
#define CBL (CBH + 130*CROWB)         // 71840
#define CBUF (CBL + 130*CROWB)        // 82240
#define CONV_SMEM (2*CBUF)            // 164480

template<int MODE>
__global__ __launch_bounds__(256, 1) void conv_mma_kernel(
    const __nv_bfloat16* __restrict__ xh_g, const __nv_bfloat16* __restrict__ xl_g,
    const __nv_bfloat16* __restrict__ wth,  const __nv_bfloat16* __restrict__ wtl,
    const float* __restrict__ bias, const float* __restrict__ resid,
    float* __restrict__ outf,
    __nv_bfloat16* __restrict__ outh, __nv_bfloat16* __restrict__ outl)
{
    extern __shared__ __align__(16) unsigned char SM[];

    const int tid  = threadIdx.x;
    const int wid  = tid >> 5;
    const int lane = tid & 31;
    const int g    = lane >> 2;
    const int tq   = lane & 3;
    const int n0   = blockIdx.x * 128;     // (b, t-tile)
    const int m0   = blockIdx.y * 128;     // eo tile
    const int b    = n0 >> 9;
    const int t0   = n0 & 511;
    const int wm   = wid & 1;
    const int wn   = wid >> 1;
    const uint32_t smbase = smem_u32(SM);

    const __nv_bfloat16* __restrict__ xh_b = xh_g + (size_t)b * Ee * Tt;
    const __nv_bfloat16* __restrict__ xl_b = xl_g + (size_t)b * Ee * Tt;

    float acc[4][4][4];
    #pragma unroll
    for (int i = 0; i < 4; i++)
        #pragma unroll
        for (int j = 0; j < 4; j++)
            #pragma unroll
            for (int q = 0; q < 4; q++) acc[i][j][q] = 0.f;

    // ---- chunk loader ----
    auto issue = [&](int kbeg, int bsel) {
        uint32_t base = smbase + bsel * CBUF;
        // A: weights, 3 taps x 128 eo x 32 ei, hi+lo = 3072 x 16B, 12/thread
        #pragma unroll
        for (int i = 0; i < 12; i++) {
            int idx = tid + 256 * i;
            int hl  = (idx >= 1536);
            int r   = hl ? (idx - 1536) : idx;     // FIXED: 1536 not pow2, no mask
            int row = r >> 2;                      // 0..383 = dk*128+eo
            int q   = r & 3;
            int dk  = row >> 7;
            int eo  = row & 127;
            const __nv_bfloat16* gsrc =
                (hl ? wtl : wth) + (size_t)dk * (Ee * Ee) + (size_t)(m0 + eo) * Ee + kbeg + q * 8;
            uint32_t daddr = base + (hl ? CAL : CAH) + row * CROWB + q * 16;
            asm volatile("cp.async.cg.shared.global [%0], [%1], 16;"
                         :: "r"(daddr), "l"(gsrc));
        }
        asm volatile("cp.async.commit_group;" ::: "memory");

        unsigned char* bb = SM + bsel * CBUF;
        // B aligned: 32 ei x 64 bf16x2 (t0..t0+127), hi+lo = 4096 units, 16/thread
        #pragma unroll
        for (int i = 0; i < 16; i++) {
            int idx = tid + 256 * i;
            int hl  = (idx >= 2048);
            int r   = idx & 2047;
            int ei  = r >> 6;
            int u   = r & 63;
            const __nv_bfloat16* s = (hl ? xl_b : xh_b) + (size_t)(kbeg + ei) * Tt + t0 + u * 2;
            uint32_t v = *(const uint32_t*)s;
            unsigned char* d = bb + (hl ? CBL : CBH) + (1 + u * 2) * CROWB + ei * 2;
            *(unsigned short*)d            = (unsigned short)(v & 0xffffu);
            *(unsigned short*)(d + CROWB)  = (unsigned short)(v >> 16);
        }
        // B halo rows (t_local 0 and 129)
        if (tid < 128) {
            int ei   = tid & 31;
            int hl   = (tid >> 5) & 1;
            int side = tid >> 6;
            const __nv_bfloat16* s = hl ? xl_b : xh_b;
            unsigned short v = 0;
            if (side == 0) {
                if (t0 > 0) v = *(const unsigned short*)&s[(size_t)(kbeg + ei) * Tt + t0 - 1];
            } else {
                if (t0 + 128 < Tt) v = *(const unsigned short*)&s[(size_t)(kbeg + ei) * Tt + t0 + 128];
            }
            int tl = side ? 129 : 0;
            *(unsigned short*)(bb + (hl ? CBL : CBH) + tl * CROWB + ei * 2) = v;
        }
    };

    // ---- compute one K=32 chunk ----
    auto compute = [&](int bsel) {
        const unsigned char* B0 = SM + bsel * CBUF;
        #pragma unroll
        for (int ko = 0; ko < 32; ko += 16) {
            #pragma unroll
            for (int dk = 0; dk < 3; dk++) {
                uint32_t ah[4][4], al[4][4], bh[4][2], bl[4][2];
                #pragma unroll
                for (int mt = 0; mt < 4; mt++) {
                    int row = dk * 128 + wm * 64 + mt * 16 + g;
                    const unsigned char* r = B0 + CAH + row * CROWB + (ko + tq * 2) * 2;
                    ah[mt][0] = *(const uint32_t*)r;
                    ah[mt][1] = *(const uint32_t*)(r + 8 * CROWB);
                    ah[mt][2] = *(const uint32_t*)(r + 16);
                    ah[mt][3] = *(const uint32_t*)(r + 8 * CROWB + 16);
                    const unsigned char* r2 = B0 + CAL + row * CROWB + (ko + tq * 2) * 2;
                    al[mt][0] = *(const uint32_t*)r2;
                    al[mt][1] = *(const uint32_t*)(r2 + 8 * CROWB);
                    al[mt][2] = *(const uint32_t*)(r2 + 16);
                    al[mt][3] = *(const uint32_t*)(r2 + 8 * CROWB + 16);
                }
                #pragma unroll
                for (int nt = 0; nt < 4; nt++) {
                    int row = wn * 32 + nt * 8 + g + dk;   // halo base: t_local = t+dk-1+1
                    const unsigned char* r = B0 + CBH + row * CROWB + (ko + tq * 2) * 2;
                    bh[nt][0] = *(const uint32_t*)r;
                    bh[nt][1] = *(const uint32_t*)(r + 16);
                    const unsigned char* r2 = B0 + CBL + row * CROWB + (ko + tq * 2) * 2;
                    bl[nt][0] = *(const uint32_t*)r2;
                    bl[nt][1] = *(const uint32_t*)(r2 + 16);
                }
                #pragma unroll
                for (int mt = 0; mt < 4; mt++)
                    #pragma unroll
                    for (int nt = 0; nt < 4; nt++)
                        MMA16816(acc[mt][nt], ah[mt], bh[nt]);
                #pragma unroll
                for (int mt = 0; mt < 4; mt++)
                    #pragma unroll
                    for (int nt = 0; nt < 4; nt++)
                        MMA16816(acc[mt][nt], ah[mt], bl[nt]);
                #pragma unroll
                for (int mt = 0; mt < 4; mt++)
                    #pragma unroll
                    for (int nt = 0; nt < 4; nt++)
                        MMA16816(acc[mt][nt], al[mt], bh[nt]);
            }
        }
    };

    const int NC = Ee / 32;   // 16
    issue(0, 0);
    for (int c = 0; c < NC; c++) {
        if (c + 1 < NC) {
            issue((c + 1) * 32, (c + 1) & 1);
            asm volatile("cp.async.wait_group 1;" ::: "memory");
        } else {
            asm volatile("cp.async.wait_group 0;" ::: "memory");
        }
        __syncthreads();
        compute(c & 1);
        __syncthreads();
    }

    // ---- epilogue: bias(eo) + relu + residual ----
    #pragma unroll
    for (int mt = 0; mt < 4; mt++) {
        const int eo0 = m0 + wm * 64 + mt * 16 + g;
        const int eo1 = eo0 + 8;
        const float b0v = bias[eo0], b1v = bias[eo1];
        #pragma unroll
        for (int nt = 0; nt < 4; nt++) {
            const int n = t0 + wn * 32 + nt * 8 + tq * 2;
            float v00 = acc[mt][nt][0] + b0v;   // (eo0, n)
            float v01 = acc[mt][nt][1] + b0v;   // (eo0, n+1)
            float v10 = acc[mt][nt][2] + b1v;   // (eo1, n)
            float v11 = acc[mt][nt][3] + b1v;   // (eo1, n+1)
            v00 = (v00 > 0.f) ? v00 : 0.f;
            v01 = (v01 > 0.f) ? v01 : 0.f;
            v10 = (v10 > 0.f) ? v10 : 0.f;
            v11 = (v11 > 0.f) ? v11 : 0.f;
            size_t i00 = ((size_t)b * Ee + eo0) * Tt + n;
            size_t i10 = ((size_t)b * Ee + eo1) * Tt + n;
            v00 += resid[i00];     v01 += resid[i00 + 1];
            v10 += resid[i10];     v11 += resid[i10 + 1];
            if (MODE == 0) {
                outf[i00] = v00; outf[i00 + 1] = v01;
                outf[i10] = v10; outf[i10 + 1] = v11;
                __nv_bfloat16 h00 = __float2bfloat16(v00);
                __nv_bfloat16 h01 = __float2bfloat16(v01);
                __nv_bfloat16 h10 = __float2bfloat16(v10);
                __nv_bfloat16 h11 = __float2bfloat16(v11);
                outh[i00] = h00; outh[i00 + 1] = h01;
                outh[i10] = h10; outh[i10 + 1] = h11;
                outl[i00]     = __float2bfloat16(v00 - __bfloat162float(h00));
                outl[i00 + 1] = __float2bfloat16(v01 - __bfloat162float(h01));
                outl[i10]     = __float2bfloat16(v10 - __bfloat162float(h10));
                outl[i10 + 1] = __float2bfloat16(v11 - __bfloat162float(h11));
            } else {
                outf[((size_t)b * Tt + n)     * Ee + eo0] = v00;
                outf[((size_t)b * Tt + n + 1) * Ee + eo0] = v01;
                outf[((size_t)b * Tt + n)     * Ee + eo1] = v10;
                outf[((size_t)b * Tt + n + 1) * Ee + eo1] = v11;
            }
        }
    }
}

// ---------------------------------------------------------------------------
// Span max gather -> bf16 hi/lo (feeds FC1)
// ---------------------------------------------------------------------------
__global__ __launch_bounds__(128) void span_kernel(
    const int* __restrict__ bidx,
    const int* __restrict__ hidx, const int* __restrict__ hspan,
    const int* __restrict__ tidx, const int* __restrict__ tspan)
{
    const int p  = blockIdx.x;
    const int e4 = threadIdx.x;
    const int b  = bidx[p];
    const float4* __restrict__ base = (const float4*)g_xbte + (size_t)b * Tt * (Ee / 4);

    const int h0 = hidx[p], hs = hspan[p];
    const int t0 = tidx[p], ts = tspan[p];

    float4 hm = make_float4(-INFINITY, -INFINITY, -INFINITY, -INFINITY);
    for (int s = 0; s < hs; s++) {
        float4 v = base[(size_t)(h0 + s) * (Ee / 4) + e4];
        hm.x = fmaxf(hm.x, v.x); hm.y = fmaxf(hm.y, v.y);
        hm.z = fmaxf(hm.z, v.z); hm.w = fmaxf(hm.w, v.w);
    }
    float4 tm = make_float4(-INFINITY, -INFINITY, -INFINITY, -INFINITY);
    for (int s = 0; s < ts; s++) {
        float4 v = base[(size_t)(t0 + s) * (Ee / 4) + e4];
        tm.x = fmaxf(tm.x, v.x); tm.y = fmaxf(tm.y, v.y);
        tm.z = fmaxf(tm.z, v.z); tm.w = fmaxf(tm.w, v.w);
    }
    float o[4] = {hm.x + tm.x, hm.y + tm.y, hm.z + tm.z, hm.w + tm.w};

    size_t off = (size_t)p * Ee + e4 * 4;
    #pragma unroll
    for (int j = 0; j < 4; j++) {
        __nv_bfloat16 h = __float2bfloat16(o[j]);
        __nv_bfloat16 l = __float2bfloat16(o[j] - __bfloat162float(h));
        g_mx_h[off + j] = h;
        g_mx_l[off + j] = l;
    }
}

// ---------------------------------------------------------------------------
// Tensor-core bf16x3 NT GEMM (FC1/FC2) — unchanged from round 7
// ---------------------------------------------------------------------------
#define SROW 40
#define SEC_ELEMS (128*SROW)
#define SEC_BYTES (SEC_ELEMS*2)
#define BUF_BYTES (4*SEC_BYTES)
#define FC_SMEM   (2*BUF_BYTES)

template<bool HILO>
__global__ __launch_bounds__(256, 1) void fc_mma_kernel(
    const __nv_bfloat16* __restrict__ Ah, const __nv_bfloat16* __restrict__ Al,
    const __nv_bfloat16* __restrict__ Bh, const __nv_bfloat16* __restrict__ Bl,
    const float* __restrict__ bias, int K, int N,
    float* __restrict__ Cf,
    __nv_bfloat16* __restrict__ Ch, __nv_bfloat16* __restrict__ Cl)
{
    extern __shared__ __align__(16) unsigned char SM[];

    const int tid  = threadIdx.x;
    const int wid  = tid >> 5;
    const int lane = tid & 31;
    const int g    = lane >> 2;
    const int t    = lane & 3;
    const int n0   = blockIdx.x * 128;
    const int m0   = blockIdx.y * 128;
    const int wm   = wid & 1;
    const int wn   = wid >> 1;
    const uint32_t smbase = smem_u32(SM);

    float acc[4][4][4];
    #pragma unroll
    for (int i = 0; i < 4; i++)
        #pragma unroll
        for (int j = 0; j < 4; j++)
            #pragma unroll
            for (int q = 0; q < 4; q++) acc[i][j][q] = 0.f;

    auto issue_chunk = [&](int kbeg, int bsel) {
        uint32_t base = smbase + bsel * BUF_BYTES;
        #pragma unroll
        for (int i = 0; i < 8; i++) {
            int idx = tid + 256 * i;
            int sec = idx >> 9;
            int rem = idx & 511;
            int row = rem >> 2;
            int q   = rem & 3;
            const __nv_bfloat16* gsrc;
            if (sec == 0)      gsrc = Ah + (size_t)(m0 + row) * K + kbeg + q * 8;
            else if (sec == 1) gsrc = Al + (size_t)(m0 + row) * K + kbeg + q * 8;
            else if (sec == 2) gsrc = Bh + (size_t)(n0 + row) * K + kbeg + q * 8;
            else               gsrc = Bl + (size_t)(n0 + row) * K + kbeg + q * 8;
            uint32_t daddr = base + sec * SEC_BYTES + row * (SROW * 2) + q * 16;
            asm volatile("cp.async.cg.shared.global [%0], [%1], 16;"
                         :: "r"(daddr), "l"(gsrc));
        }
        asm volatile("cp.async.commit_group;" ::: "memory");
    };

    auto compute_chunk = [&](int bsel) {
        const __nv_bfloat16* sAh = (const __nv_bfloat16*)(SM + bsel * BUF_BYTES);
        const __nv_bfloat16* sAl = sAh + SEC_ELEMS;
        const __nv_bfloat16* sBh = sAl + SEC_ELEMS;
        const __nv_bfloat16* sBl = sBh + SEC_ELEMS;

        #pragma unroll
        for (int ko = 0; ko < 32; ko += 16) {
            uint32_t ah[4][4], al[4][4], bh[4][2], bl[4][2];
            #pragma unroll
            for (int mt = 0; mt < 4; mt++) {
                const __nv_bfloat16* r = sAh + (wm * 64 + mt * 16 + g) * SROW + ko + t * 2;
                ah[mt][0] = *(const uint32_t*)r;
                ah[mt][1] = *(const uint32_t*)(r + 8 * SROW);
                ah[mt][2] = *(const uint32_t*)(r + 8);
                ah[mt][3] = *(const uint32_t*)(r + 8 * SROW + 8);
                const __nv_bfloat16* r2 = sAl + (wm * 64 + mt * 16 + g) * SROW + ko + t * 2;
                al[mt][0] = *(const uint32_t*)r2;
                al[mt][1] = *(const uint32_t*)(r2 + 8 * SROW);
                al[mt][2] = *(const uint32_t*)(r2 + 8);
                al[mt][3] = *(const uint32_t*)(r2 + 8 * SROW + 8);
            }
            #pragma unroll
            for (int nt = 0; nt < 4; nt++) {
                const __nv_bfloat16* r = sBh + (wn * 32 + nt * 8 + g) * SROW + ko + t * 2;
                bh[nt][0] = *(const uint32_t*)r;
                bh[nt][1] = *(const uint32_t*)(r + 8);
                const __nv_bfloat16* r2 = sBl + (wn * 32 + nt * 8 + g) * SROW + ko + t * 2;
                bl[nt][0] = *(const uint32_t*)r2;
                bl[nt][1] = *(const uint32_t*)(r2 + 8);
            }
            #pragma unroll
            for (int mt = 0; mt < 4; mt++)
                #pragma unroll
                for (int nt = 0; nt < 4; nt++)
                    MMA16816(acc[mt][nt], ah[mt], bh[nt]);
            #pragma unroll
            for (int mt = 0; mt < 4; mt++)
                #pragma unroll
                for (int nt = 0; nt < 4; nt++)
                    MMA16816(acc[mt][nt], ah[mt], bl[nt]);
            #pragma unroll
            for (int mt = 0; mt < 4; mt++)
                #pragma unroll
                for (int nt = 0; nt < 4; nt++)
                    MMA16816(acc[mt][nt], al[mt], bh[nt]);
        }
    };

    const int NC = K / 32;
    issue_chunk(0, 0);
    for (int c = 0; c < NC; c++) {
        if (c + 1 < NC) {
            issue_chunk((c + 1) * 32, (c + 1) & 1);
            asm volatile("cp.async.wait_group 1;" ::: "memory");
        } else {
            asm volatile("cp.async.wait_group 0;" ::: "memory");
        }
        __syncthreads();
        compute_chunk(c & 1);
        __syncthreads();
    }

    #pragma unroll
    for (int mt = 0; mt < 4; mt++) {
        const int m = m0 + wm * 64 + mt * 16 + g;
        #pragma unroll
        for (int nt = 0; nt < 4; nt++) {
            const int n = n0 + wn * 32 + nt * 8 + t * 2;
            float b0 = bias[n], b1 = bias[n + 1];
            float v00 = acc[mt][nt][0] + b0;
            float v01 = acc[mt][nt][1] + b1;
            float v10 = acc[mt][nt][2] + b0;
            float v11 = acc[mt][nt][3] + b1;
            v00 = (v00 > 0.f) ? v00 : 0.f;
            v01 = (v01 > 0.f) ? v01 : 0.f;
            v10 = (v10 > 0.f) ? v10 : 0.f;
            v11 = (v11 > 0.f) ? v11 : 0.f;
            if (HILO) {
                __nv_bfloat16 h00 = __float2bfloat16(v00);
                __nv_bfloat16 h01 = __float2bfloat16(v01);
                __nv_bfloat16 h10 = __float2bfloat16(v10);
                __nv_bfloat16 h11 = __float2bfloat16(v11);
                __nv_bfloat162 hp0; hp0.x = h00; hp0.y = h01;
                __nv_bfloat162 hp1; hp1.x = h10; hp1.y = h11;
                __nv_bfloat162 lp0;
                lp0.x = __float2bfloat16(v00 - __bfloat162float(h00));
                lp0.y = __float2bfloat16(v01 - __bfloat162float(h01));
                __nv_bfloat162 lp1;
                lp1.x = __float2bfloat16(v10 - __bfloat162float(h10));
                lp1.y = __float2bfloat16(v11 - __bfloat162float(h11));
                *(__nv_bfloat162*)(Ch + (size_t)m * N + n)       = hp0;
                *(__nv_bfloat162*)(Cl + (size_t)m * N + n)       = lp0;
                *(__nv_bfloat162*)(Ch + (size_t)(m + 8) * N + n) = hp1;
                *(__nv_bfloat162*)(Cl + (size_t)(m + 8) * N + n) = lp1;
            } else {
                float2 f0 = make_float2(v00, v01);
                float2 f1 = make_float2(v10, v11);
                *(float2*)(Cf + (size_t)m * N + n)       = f0;
                *(float2*)(Cf + (size_t)(m + 8) * N + n) = f1;
            }
        }
    }
}

// ---------------------------------------------------------------------------
// FC3 split-K GEMM (scalar) + reduce — unchanged
// ---------------------------------------------------------------------------
__global__ __launch_bounds__(256, 2) void fc3_splitk_kernel(
    const float* __restrict__ A,
    const float* __restrict__ Wr)
{
    __shared__ float As[2][8][128];
    __shared__ float Bs[2][8][32];

    const int tid = threadIdx.x;
    const int ks  = blockIdx.x;
    const int m0  = blockIdx.y * 128;
    const int kbeg = ks * (Hh / KSPLIT);
    const int tx = tid & 7;
    const int ty = tid >> 3;

    float acc[4][4];
    #pragma unroll
    for (int i = 0; i < 4; i++)
        #pragma unroll
        for (int j = 0; j < 4; j++) acc[i][j] = 0.f;

    const int r = tid >> 1;
    const int s = (tid & 1) * 4;
    const float* __restrict__ Arow = A + (size_t)(m0 + r) * Hh + kbeg + s;
    const float* __restrict__ Brow = Wr + (size_t)(tid >> 1) * Hh + kbeg + ((tid & 1) * 4);

    float4 a_n; float4 b_n = make_float4(0.f,0.f,0.f,0.f);

    a_n = *(const float4*)&Arow[0];
    if (tid < 64) b_n = *(const float4*)&Brow[0];
    As[0][s + 0][r] = a_n.x; As[0][s + 1][r] = a_n.y;
    As[0][s + 2][r] = a_n.z; As[0][s + 3][r] = a_n.w;
    if (tid < 64) {
        int bn = tid >> 1, bs = (tid & 1) * 4;
        Bs[0][bs + 0][bn] = b_n.x; Bs[0][bs + 1][bn] = b_n.y;
        Bs[0][bs + 2][bn] = b_n.z; Bs[0][bs + 3][bn] = b_n.w;
    }
    __syncthreads();

    int buf = 0;
    const int KC = Hh / KSPLIT;
    for (int k0 = 8; k0 <= KC; k0 += 8) {
        const bool more = (k0 < KC);
        if (more) {
            a_n = *(const float4*)&Arow[k0];
            if (tid < 64) b_n = *(const float4*)&Brow[k0];
        }

        #pragma unroll
        for (int k = 0; k < 8; k++) {
            float4 a0 = *(const float4*)&As[buf][k][ty * 4];
            float4 b0 = *(const float4*)&Bs[buf][k][tx * 4];
            float av[4] = {a0.x, a0.y, a0.z, a0.w};
            float bv[4] = {b0.x, b0.y, b0.z, b0.w};
            #pragma unroll
            for (int ii = 0; ii < 4; ii++)
                #pragma unroll
                for (int jj = 0; jj < 4; jj++)
                    acc[ii][jj] += av[ii] * bv[jj];
        }

        if (more) {
            int nb = buf ^ 1;
            As[nb][s + 0][r] = a_n.x; As[nb][s + 1][r] = a_n.y;
            As[nb][s + 2][r] = a_n.z; As[nb][s + 3][r] = a_n.w;
            if (tid < 64) {
                int bn = tid >> 1, bs = (tid & 1) * 4;
                Bs[nb][bs + 0][bn] = b_n.x; Bs[nb][bs + 1][bn] = b_n.y;
                Bs[nb][bs + 2][bn] = b_n.z; Bs[nb][bs + 3][bn] = b_n.w;
            }
            buf = nb;
            __syncthreads();
        }
    }

    float* __restrict__ part = (float*)g_fc3p + (size_t)ks * Pp * Rr;
    #pragma unroll
    for (int ii = 0; ii < 4; ii++) {
        int m = m0 + ty * 4 + ii;
        #pragma unroll
        for (int jj = 0; jj < 4; jj++) {
            int nn = tx * 4 + jj;
            part[(size_t)m * Rr + nn] = acc[ii][jj];
        }
    }
}

__global__ void fc3_reduce_kernel(const float* __restrict__ br,
                                  float* __restrict__ out)
{
    int i = blockIdx.x * blockDim.x + threadIdx.x;
    if (i < Pp * Rr) {
        const float* p = (const float*)g_fc3p;
        float v = p[i] + p[i + Pp*Rr] + p[i + 2*Pp*Rr] + p[i + 3*Pp*Rr];
        out[i] = v + br[i & (Rr - 1)];
    }
}

// ---------------------------------------------------------------------------
__global__ void pack_kernel(const float* __restrict__ trig,
                            const int* __restrict__ labels,
                            float* __restrict__ out, int out_size)
{
    int i = blockIdx.x * blockDim.x + threadIdx.x;
    const int PR = Pp * Rr;
    const int BT = Bb * Tt;
    if (out_size >= PR + BT && i < BT)        out[PR + i]      = trig[i];
    if (out_size >= PR + BT + Pp && i < Pp)   out[PR + BT + i] = (float)labels[i];
}

// ---------------------------------------------------------------------------
extern "C" void kernel_launch(void* const* d_in, const int* in_sizes, int n_in,
                              void* d_out, int out_size)
{
    const float* x     = (const float*)d_in[0];
    const float* trig  = (const float*)d_in[1];
    const int*   bidx  = (const int*)  d_in[2];
    const int*   hidx  = (const int*)  d_in[3];
    const int*   hspan = (const int*)  d_in[4];
    const int*   tidx  = (const int*)  d_in[5];
    const int*   tspan = (const int*)  d_in[6];
    const int*   labels= (const int*)  d_in[7];
    const float* c1w   = (const float*)d_in[8];
    const float* c1b   = (const float*)d_in[9];
    const float* c2w   = (const float*)d_in[10];
    const float* c2b   = (const float*)d_in[11];
    const float* w1    = (const float*)d_in[12];
    const float* b1    = (const float*)d_in[13];
    const float* w2    = (const float*)d_in[14];
    const float* b2    = (const float*)d_in[15];
    const float* wr    = (const float*)d_in[16];
    const float* br    = (const float*)d_in[17];
    float* out = (float*)d_out;

    __nv_bfloat16 *pxh, *pxl, *px1h, *px1l, *pwt1h, *pwt1l, *pwt2h, *pwt2l;
    __nv_bfloat16 *pmxh, *pmxl, *pw1h, *pw1l, *pw2h, *pw2l, *ph1h, *ph1l;
    float *px1, *pxbte, *ph2;
    cudaGetSymbolAddress((void**)&pxh,   g_xh);
    cudaGetSymbolAddress((void**)&pxl,   g_xl);
    cudaGetSymbolAddress((void**)&px1h,  g_x1h);
    cudaGetSymbolAddress((void**)&px1l,  g_x1l);
    cudaGetSymbolAddress((void**)&pwt1h, g_wt1h);
    cudaGetSymbolAddress((void**)&pwt1l, g_wt1l);
    cudaGetSymbolAddress((void**)&pwt2h, g_wt2h);
    cudaGetSymbolAddress((void**)&pwt2l, g_wt2l);
    cudaGetSymbolAddress((void**)&pmxh,  g_mx_h);
    cudaGetSymbolAddress((void**)&pmxl,  g_mx_l);
    cudaGetSymbolAddress((void**)&pw1h,  g_w1h);
    cudaGetSymbolAddress((void**)&pw1l,  g_w1l);
    cudaGetSymbolAddress((void**)&pw2h,  g_w2h);
    cudaGetSymbolAddress((void**)&pw2l,  g_w2l);
    cudaGetSymbolAddress((void**)&ph1h,  g_h1h);
    cudaGetSymbolAddress((void**)&ph1l,  g_h1l);
    cudaGetSymbolAddress((void**)&px1,   g_x1);
    cudaGetSymbolAddress((void**)&pxbte, g_xbte);
    cudaGetSymbolAddress((void**)&ph2,   g_h2);

    static int smem_set = 0;
    if (!smem_set) {
        cudaFuncSetAttribute(fc_mma_kernel<true>,
                             cudaFuncAttributeMaxDynamicSharedMemorySize, FC_SMEM);
        cudaFuncSetAttribute(fc_mma_kernel<false>,
                             cudaFuncAttributeMaxDynamicSharedMemorySize, FC_SMEM);
        cudaFuncSetAttribute(conv_mma_kernel<0>,
                             cudaFuncAttributeMaxDynamicSharedMemorySize, CONV_SMEM);
        cudaFuncSetAttribute(conv_mma_kernel<1>,
                             cudaFuncAttributeMaxDynamicSharedMemorySize, CONV_SMEM);
        smem_set = 1;
    }

    // Conversions
    cvt_hilo_kernel<<<(Bb*Ee*Tt + 255)/256, 256>>>(x, pxh, pxl, Bb*Ee*Tt);
    cvt_wt_kernel<<<(Ee*Ee*3 + 255)/256, 256>>>(c1w, pwt1h, pwt1l);
    cvt_wt_kernel<<<(Ee*Ee*3 + 255)/256, 256>>>(c2w, pwt2h, pwt2l);
    cvt_hilo_kernel<<<(Hh*Ee + 255)/256, 256>>>(w1, pw1h, pw1l, Hh*Ee);
    cvt_hilo_kernel<<<(Hh*Hh + 255)/256, 256>>>(w2, pw2h, pw2l, Hh*Hh);

    // Conv blocks (tensor cores)
    {
        dim3 grid((Bb * Tt) / 128, Ee / 128);   // 64 x 4
        conv_mma_kernel<0><<<grid, 256, CONV_SMEM>>>(
            pxh, pxl, pwt1h, pwt1l, c1b, x, px1, px1h, px1l);
        conv_mma_kernel<1><<<grid, 256, CONV_SMEM>>>(
            px1h, px1l, pwt2h, pwt2l, c2b, px1, pxbte, nullptr, nullptr);
    }

    // Span max -> bf16 hi/lo
    span_kernel<<<Pp, 128>>>(bidx, hidx, hspan, tidx, tspan);

    // FC1 (mma bf16x3): (P,512)x(1024,512)^T -> h1 hi/lo, relu
    {
        dim3 grid(Hh / 128, Pp / 128);
        fc_mma_kernel<true><<<grid, 256, FC_SMEM>>>(
            pmxh, pmxl, pw1h, pw1l, b1, Ee, Hh, nullptr, ph1h, ph1l);
    }
    // FC2 (mma bf16x3): (P,1024)x(1024,1024)^T -> h2 fp32, relu
    {
        dim3 grid(Hh / 128, Pp / 128);
        fc_mma_kernel<false><<<grid, 256, FC_SMEM>>>(
            ph1h, ph1l, pw2h, pw2l, b2, Hh, Hh, ph2, nullptr, nullptr);
    }
    // FC3: split-K + reduce into d_out
    {
        dim3 grid(KSPLIT, Pp / 128);
        fc3_splitk_kernel<<<grid, 256>>>(ph2, wr);
        fc3_reduce_kernel<<<(Pp * Rr + 255) / 256, 256>>>(br, out);
    }
    // trig_attn + rel_labels passthrough
    pack_kernel<<<(8192 + 255) / 256, 256>>>(trig, labels, out, out_size);
}

// round 10
// speedup vs baseline: 2.3359x; 1.0137x over previous
#include <cuda_runtime.h>
#include <cuda_bf16.h>
#include <math.h>
#include <stdint.h>

// Problem constants
#define Bb 16
#define Ee 512
#define Tt 512
#define Hh 1024
#define Rr 32
#define Pp 8192
#define Ww 3
#define KSPLIT 4

// bf16 m16n8k16 tensor-core MMA (baseline PTX, valid on sm_103)
#define MMA16816(C, A, B) \
    asm volatile("mma.sync.aligned.m16n8k16.row.col.f32.bf16.bf16.f32 " \
        "{%0,%1,%2,%3}, {%4,%5,%6,%7}, {%8,%9}, {%0,%1,%2,%3};" \
        : "+f"((C)[0]), "+f"((C)[1]), "+f"((C)[2]), "+f"((C)[3]) \
        : "r"((A)[0]), "r"((A)[1]), "r"((A)[2]), "r"((A)[3]), \
          "r"((B)[0]), "r"((B)[1]))

// ldmatrix: 4x 8x8 b16 matrices (A 16x16 tile, or two B n8k16 tiles)
#define LDSM_X4(R0, R1, R2, R3, addr) \
    asm volatile("ldmatrix.sync.aligned.m8n8.x4.shared.b16 {%0,%1,%2,%3}, [%4];" \
        : "=r"(R0), "=r"(R1), "=r"(R2), "=r"(R3) : "r"(addr))

__device__ __forceinline__ uint32_t smem_u32(const void* p) {
    uint32_t a;
    asm("{ .reg .u64 t; cvta.to.shared.u64 t, %1; cvt.u32.u64 %0, t; }" : "=r"(a) : "l"(p));
    return a;
}

// Scratch (device globals: allocation-free per harness rules)
__device__ float g_x1[Bb*Ee*Tt];                 // conv1 out fp32 (B,E,T)
__device__ float g_xbte[Bb*Tt*Ee];               // conv2 out fp32 (B,T,E)
__device__ __nv_bfloat16 g_xh[Bb*Ee*Tt];         // input x hi/lo (B,E,T)
__device__ __nv_bfloat16 g_xl[Bb*Ee*Tt];
__device__ __nv_bfloat16 g_x1h[Bb*Ee*Tt];        // conv1 out hi/lo (B,E,T)
__device__ __nv_bfloat16 g_x1l[Bb*Ee*Tt];
__device__ __nv_bfloat16 g_wt1h[3*Ee*Ee];        // conv weights [dk][eo][ei]
__device__ __nv_bfloat16 g_wt1l[3*Ee*Ee];
__device__ __nv_bfloat16 g_wt2h[3*Ee*Ee];
__device__ __nv_bfloat16 g_wt2l[3*Ee*Ee];
__device__ __nv_bfloat16 g_mx_h[Pp*Ee];
__device__ __nv_bfloat16 g_mx_l[Pp*Ee];
__device__ __nv_bfloat16 g_w1h[Hh*Ee];
__device__ __nv_bfloat16 g_w1l[Hh*Ee];
__device__ __nv_bfloat16 g_w2h[Hh*Hh];
__device__ __nv_bfloat16 g_w2l[Hh*Hh];
__device__ __nv_bfloat16 g_h1h[Pp*Hh];
__device__ __nv_bfloat16 g_h1l[Pp*Hh];
__device__ float g_h2[Pp*Hh];
__device__ float g_fc3p[KSPLIT*Pp*Rr];

// fp32 -> bf16 hi/lo (elementwise)
__global__ void cvt_hilo_kernel(const float* __restrict__ in,
                                __nv_bfloat16* __restrict__ hi,
                                __nv_bfloat16* __restrict__ lo, int n)
{
    int i = blockIdx.x * blockDim.x + threadIdx.x;
    if (i < n) {
        float x = in[i];
        __nv_bfloat16 h = __float2bfloat16(x);
        hi[i] = h;
        lo[i] = __float2bfloat16(x - __bfloat162float(h));
    }
}

// conv weights (eo,ei,dk) -> transposed [dk][eo][ei] hi/lo
__global__ void cvt_wt_kernel(const float* __restrict__ w,
                              __nv_bfloat16* __restrict__ th,
                              __nv_bfloat16* __restrict__ tl)
{
    int i = blockIdx.x * blockDim.x + threadIdx.x;
    if (i < Ee * Ee * 3) {
        int eo  = i / (Ee * 3);
        int rem = i - eo * (Ee * 3);
        int ei  = rem / 3;
        int dk  = rem - ei * 3;
        float x = w[i];
        __nv_bfloat16 h = __float2bfloat16(x);
        int o = dk * (Ee * Ee) + eo * Ee + ei;
        th[o] = h;
        tl[o] = __float2bfloat16(x - __bfloat162float(h));
    }
}

// ---------------------------------------------------------------------------
// Conv residual block via mma.sync bf16x3 + ldmatrix fragment loads.
// Layouts identical to round 9; only the fragment-load path changed.
// ---------------------------------------------------------------------------
#define CROWB 80
#define CAH 0
#define CAL (384*CROWB)
#define CBH (2*384*CROWB)
#define CBL (CBH + 130*CROWB)
#define CBUF (CBL + 130*CROWB)
#define CONV_SMEM (2*CBUF)

template<int MODE>
__global__ __launch_bounds__(256, 1) void conv_mma_kernel(
    const __nv_bfloat16* __restrict__ xh_g, const __nv_bfloat16* __restrict__ xl_g,
    const __nv_bfloat16* __restrict__ wth,  const __nv_bfloat16* __restrict__ wtl,
    const float* __restrict__ bias, const float* __restrict__ resid,
    float* __restrict__ outf,
    __nv_bfloat16* __restrict__ outh, __nv_bfloat16* __restrict__ outl)
{
    extern __shared__ __align__(16) unsigned char SM[];

    const int tid  = threadIdx.x;
    const int wid  = tid >> 5;
    const int lane = tid & 31;
    const int g    = lane >> 2;
    const int tq   = lane & 3;
    const int n0   = blockIdx.x * 128;
    const int m0   = blockIdx.y * 128;
    const int b    = n0 >> 9;
    const int t0   = n0 & 511;
    const int wm   = wid & 1;
    const int wn   = wid >> 1;
    const uint32_t smbase = smem_u32(SM);

    // ldmatrix per-lane offsets
    const int lrow = lane & 15;          // A row within 16-tile
    const int lkh  = lane >> 4;          // A k-half
    const int brow = lane & 7;           // B row within 8
    const int bkh  = (lane >> 3) & 1;    // B k-half
    const int bts  = lane >> 4;          // B tile select within pair

    const __nv_bfloat16* __restrict__ xh_b = xh_g + (size_t)b * Ee * Tt;
    const __nv_bfloat16* __restrict__ xl_b = xl_g + (size_t)b * Ee * Tt;

    float acc[4][4][4];
    #pragma unroll
    for (int i = 0; i < 4; i++)
        #pragma unroll
        for (int j = 0; j < 4; j++)
            #pragma unroll
            for (int q = 0; q < 4; q++) acc[i][j][q] = 0.f;

    // ---- chunk loader (unchanged from round 9) ----
    auto issue = [&](int kbeg, int bsel) {
        uint32_t base = smbase + bsel * CBUF;
        #pragma unroll
        for (int i = 0; i < 12; i++) {
            int idx = tid + 256 * i;
            int hl  = (idx >= 1536);
            int r   = hl ? (idx - 1536) : idx;
            int row = r >> 2;
            int q   = r & 3;
            int dk  = row >> 7;
            int eo  = row & 127;
            const __nv_bfloat16* gsrc =
                (hl ? wtl : wth) + (size_t)dk * (Ee * Ee) + (size_t)(m0 + eo) * Ee + kbeg + q * 8;
            uint32_t daddr = base + (hl ? CAL : CAH) + row * CROWB + q * 16;
            asm volatile("cp.async.cg.shared.global [%0], [%1], 16;"
                         :: "r"(daddr), "l"(gsrc));
        }
        asm volatile("cp.async.commit_group;" ::: "memory");

        unsigned char* bb = SM + bsel * CBUF;
        #pragma unroll
        for (int i = 0; i < 16; i++) {
            int idx = tid + 256 * i;
            int hl  = (idx >= 2048);
            int r   = idx & 2047;
            int ei  = r >> 6;
            int u   = r & 63;
            const __nv_bfloat16* s = (hl ? xl_b : xh_b) + (size_t)(kbeg + ei) * Tt + t0 + u * 2;
            uint32_t v = *(const uint32_t*)s;
            unsigned char* d = bb + (hl ? CBL : CBH) + (1 + u * 2) * CROWB + ei * 2;
            *(unsigned short*)d            = (unsigned short)(v & 0xffffu);
            *(unsigned short*)(d + CROWB)  = (unsigned short)(v >> 16);
        }
        if (tid < 128) {
            int ei   = tid & 31;
            int hl   = (tid >> 5) & 1;
            int side = tid >> 6;
            const __nv_bfloat16* s = hl ? xl_b : xh_b;
            unsigned short v = 0;
            if (side == 0) {
                if (t0 > 0) v = *(const unsigned short*)&s[(size_t)(kbeg + ei) * Tt + t0 - 1];
            } else {
                if (t0 + 128 < Tt) v = *(const unsigned short*)&s[(size_t)(kbeg + ei) * Tt + t0 + 128];
            }
            int tl = side ? 129 : 0;
            *(unsigned short*)(bb + (hl ? CBL : CBH) + tl * CROWB + ei * 2) = v;
        }
    };

    // ---- compute one K=32 chunk (ldmatrix) ----
    auto compute = [&](int bsel) {
        const uint32_t base = smbase + bsel * CBUF;
        #pragma unroll
        for (int ko = 0; ko < 32; ko += 16) {
            #pragma unroll
            for (int dk = 0; dk < 3; dk++) {
                uint32_t ah[4][4], al[4][4], bh[4][2], bl[4][2];
                #pragma unroll
                for (int mt = 0; mt < 4; mt++) {
                    int row = dk * 128 + wm * 64 + mt * 16 + lrow;
                    uint32_t aoff = row * CROWB + (ko + 8 * lkh) * 2;
                    LDSM_X4(ah[mt][0], ah[mt][1], ah[mt][2], ah[mt][3], base + CAH + aoff);
                    LDSM_X4(al[mt][0], al[mt][1], al[mt][2], al[mt][3], base + CAL + aoff);
                }
                #pragma unroll
                for (int p = 0; p < 2; p++) {
                    int row = wn * 32 + p * 16 + bts * 8 + brow + dk;
                    uint32_t boff = row * CROWB + (ko + 8 * bkh) * 2;
                    LDSM_X4(bh[2*p][0], bh[2*p][1], bh[2*p+1][0], bh[2*p+1][1], base + CBH + boff);
                    LDSM_X4(bl[2*p][0], bl[2*p][1], bl[2*p+1][0], bl[2*p+1][1], base + CBL + boff);
                }
                #pragma unroll
                for (int mt = 0; mt < 4; mt++)
                    #pragma unroll
                    for (int nt = 0; nt < 4; nt++)
                        MMA16816(acc[mt][nt], ah[mt], bh[nt]);
                #pragma unroll
                for (int mt = 0; mt < 4; mt++)
                    #pragma unroll
                    for (int nt = 0; nt < 4; nt++)
                        MMA16816(acc[mt][nt], ah[mt], bl[nt]);
                #pragma unroll
                for (int mt = 0; mt < 4; mt++)
                    #pragma unroll
                    for (int nt = 0; nt < 4; nt++)
                        MMA16816(acc[mt][nt], al[mt], bh[nt]);
            }
        }
    };

    const int NC = Ee / 32;
    issue(0, 0);
    for (int c = 0; c < NC; c++) {
        if (c + 1 < NC) {
            issue((c + 1) * 32, (c + 1) & 1);
            asm volatile("cp.async.wait_group 1;" ::: "memory");
        } else {
            asm volatile("cp.async.wait_group 0;" ::: "memory");
        }
        __syncthreads();
        compute(c & 1);
        __syncthreads();
    }

    // ---- epilogue ----
    #pragma unroll
    for (int mt = 0; mt < 4; mt++) {
        const int eo0 = m0 + wm * 64 + mt * 16 + g;
        const int eo1 = eo0 + 8;
        const float b0v = bias[eo0], b1v = bias[eo1];
        #pragma unroll
        for (int nt = 0; nt < 4; nt++) {
            const int n = t0 + wn * 32 + nt * 8 + tq * 2;
            float v00 = acc[mt][nt][0] + b0v;
            float v01 = acc[mt][nt][1] + b0v;
            float v10 = acc[mt][nt][2] + b1v;
            float v11 = acc[mt][nt][3] + b1v;
            v00 = (v00 > 0.f) ? v00 : 0.f;
            v01 = (v01 > 0.f) ? v01 : 0.f;
            v10 = (v10 > 0.f) ? v10 : 0.f;
            v11 = (v11 > 0.f) ? v11 : 0.f;
            size_t i00 = ((size_t)b * Ee + eo0) * Tt + n;
            size_t i10 = ((size_t)b * Ee + eo1) * Tt + n;
            v00 += resid[i00];     v01 += resid[i00 + 1];
            v10 += resid[i10];     v11 += resid[i10 + 1];
            if (MODE == 0) {
                outf[i00] = v00; outf[i00 + 1] = v01;
                outf[i10] = v10; outf[i10 + 1] = v11;
                __nv_bfloat16 h00 = __float2bfloat16(v00);
                __nv_bfloat16 h01 = __float2bfloat16(v01);
                __nv_bfloat16 h10 = __float2bfloat16(v10);
                __nv_bfloat16 h11 = __float2bfloat16(v11);
                outh[i00] = h00; outh[i00 + 1] = h01;
                outh[i10] = h10; outh[i10 + 1] = h11;
                outl[i00]     = __float2bfloat16(v00 - __bfloat162float(h00));
                outl[i00 + 1] = __float2bfloat16(v01 - __bfloat162float(h01));
                outl[i10]     = __float2bfloat16(v10 - __bfloat162float(h10));
                outl[i10 + 1] = __float2bfloat16(v11 - __bfloat162float(h11));
            } else {
                outf[((size_t)b * Tt + n)     * Ee + eo0] = v00;
                outf[((size_t)b * Tt + n + 1) * Ee + eo0] = v01;
                outf[((size_t)b * Tt + n)     * Ee + eo1] = v10;
                outf[((size_t)b * Tt + n + 1) * Ee + eo1] = v11;
            }
        }
    }
}

// ---------------------------------------------------------------------------
// Span max gather -> bf16 hi/lo
// ---------------------------------------------------------------------------
__global__ __launch_bounds__(128) void span_kernel(
    const int* __restrict__ bidx,
    const int* __restrict__ hidx, const int* __restrict__ hspan,
    const int* __restrict__ tidx, const int* __restrict__ tspan)
{
    const int p  = blockIdx.x;
    const int e4 = threadIdx.x;
    const int b  = bidx[p];
    const float4* __restrict__ base = (const float4*)g_xbte + (size_t)b * Tt * (Ee / 4);

    const int h0 = hidx[p], hs = hspan[p];
    const int t0 = tidx[p], ts = tspan[p];

    float4 hm = make_float4(-INFINITY, -INFINITY, -INFINITY, -INFINITY);
    for (int s = 0; s < hs; s++) {
        float4 v = base[(size_t)(h0 + s) * (Ee / 4) + e4];
        hm.x = fmaxf(hm.x, v.x); hm.y = fmaxf(hm.y, v.y);
        hm.z = fmaxf(hm.z, v.z); hm.w = fmaxf(hm.w, v.w);
    }
    float4 tm = make_float4(-INFINITY, -INFINITY, -INFINITY, -INFINITY);
    for (int s = 0; s < ts; s++) {
        float4 v = base[(size_t)(t0 + s) * (Ee / 4) + e4];
        tm.x = fmaxf(tm.x, v.x); tm.y = fmaxf(tm.y, v.y);
        tm.z = fmaxf(tm.z, v.z); tm.w = fmaxf(tm.w, v.w);
    }
    float o[4] = {hm.x + tm.x, hm.y + tm.y, hm.z + tm.z, hm.w + tm.w};

    size_t off = (size_t)p * Ee + e4 * 4;
    #pragma unroll
    for (int j = 0; j < 4; j++) {
        __nv_bfloat16 h = __float2bfloat16(o[j]);
        __nv_bfloat16 l = __float2bfloat16(o[j] - __bfloat162float(h));
        g_mx_h[off + j] = h;
        g_mx_l[off + j] = l;
    }
}

// ---------------------------------------------------------------------------
// Tensor-core bf16x3 NT GEMM (FC1/FC2) with ldmatrix fragment loads
// ---------------------------------------------------------------------------
#define SROW 40
#define SEC_ELEMS (128*SROW)
#define SEC_BYTES (SEC_ELEMS*2)
#define BUF_BYTES (4*SEC_BYTES)
#define FC_SMEM   (2*BUF_BYTES)

template<bool HILO>
__global__ __launch_bounds__(256, 1) void fc_mma_kernel(
    const __nv_bfloat16* __restrict__ Ah, const __nv_bfloat16* __restrict__ Al,
    const __nv_bfloat16* __restrict__ Bh, const __nv_bfloat16* __restrict__ Bl,
    const float* __restrict__ bias, int K, int N,
    float* __restrict__ Cf,
    __nv_bfloat16* __restrict__ Ch, __nv_bfloat16* __restrict__ Cl)
{
    extern __shared__ __align__(16) unsigned char SM[];

    const int tid  = threadIdx.x;
    const int wid  = tid >> 5;
    const int lane = tid & 31;
    const int g    = lane >> 2;
    const int t    = lane & 3;
    const int n0   = blockIdx.x * 128;
    const int m0   = blockIdx.y * 128;
    const int wm   = wid & 1;
    const int wn   = wid >> 1;
    const uint32_t smbase = smem_u32(SM);

    const int lrow = lane & 15;
    const int lkh  = lane >> 4;
    const int brow = lane & 7;
    const int bkh  = (lane >> 3) & 1;
    const int bts  = lane >> 4;

    float acc[4][4][4];
    #pragma unroll
    for (int i = 0; i < 4; i++)
        #pragma unroll
        for (int j = 0; j < 4; j++)
            #pragma unroll
            for (int q = 0; q < 4; q++) acc[i][j][q] = 0.f;

    auto issue_chunk = [&](int kbeg, int bsel) {
        uint32_t base = smbase + bsel * BUF_BYTES;
        #pragma unroll
        for (int i = 0; i < 8; i++) {
            int idx = tid + 256 * i;
            int sec = idx >> 9;
            int rem = idx & 511;
            int row = rem >> 2;
            int q   = rem & 3;
            const __nv_bfloat16* gsrc;
            if (sec == 0)      gsrc = Ah + (size_t)(m0 + row) * K + kbeg + q * 8;
            else if (sec == 1) gsrc = Al + (size_t)(m0 + row) * K + kbeg + q * 8;
            else if (sec == 2) gsrc = Bh + (size_t)(n0 + row) * K + kbeg + q * 8;
            else               gsrc = Bl + (size_t)(n0 + row) * K + kbeg + q * 8;
            uint32_t daddr = base + sec * SEC_BYTES + row * (SROW * 2) + q * 16;
            asm volatile("cp.async.cg.shared.global [%0], [%1], 16;"
                         :: "r"(daddr), "l"(gsrc));
        }
        asm volatile("cp.async.commit_group;" ::: "memory");
    };

    auto compute_chunk = [&](int bsel) {
        const uint32_t base = smbase + bsel * BUF_BYTES;
        #pragma unroll
        for (int ko = 0; ko < 32; ko += 16) {
            uint32_t ah[4][4], al[4][4], bh[4][2], bl[4][2];
            #pragma unroll
            for (int mt = 0; mt < 4; mt++) {
                uint32_t aoff = (wm * 64 + mt * 16 + lrow) * (SROW * 2) + (ko + 8 * lkh) * 2;
                LDSM_X4(ah[mt][0], ah[mt][1], ah[mt][2], ah[mt][3], base + aoff);
                LDSM_X4(al[mt][0], al[mt][1], al[mt][2], al[mt][3], base + SEC_BYTES + aoff);
            }
            #pragma unroll
            for (int p = 0; p < 2; p++) {
                uint32_t boff = (wn * 32 + p * 16 + bts * 8 + brow) * (SROW * 2) + (ko + 8 * bkh) * 2;
                LDSM_X4(bh[2*p][0], bh[2*p][1], bh[2*p+1][0], bh[2*p+1][1],
                        base + 2 * SEC_BYTES + boff);
                LDSM_X4(bl[2*p][0], bl[2*p][1], bl[2*p+1][0], bl[2*p+1][1],
                        base + 3 * SEC_BYTES + boff);
            }
            #pragma unroll
            for (int mt = 0; mt < 4; mt++)
                #pragma unroll
                for (int nt = 0; nt < 4; nt++)
                    MMA16816(acc[mt][nt], ah[mt], bh[nt]);
            #pragma unroll
            for (int mt = 0; mt < 4; mt++)
                #pragma unroll
                for (int nt = 0; nt < 4; nt++)
                    MMA16816(acc[mt][nt], ah[mt], bl[nt]);
            #pragma unroll
            for (int mt = 0; mt < 4; mt++)
                #pragma unroll
                for (int nt = 0; nt < 4; nt++)
                    MMA16816(acc[mt][nt], al[mt], bh[nt]);
        }
    };

    const int NC = K / 32;
    issue_chunk(0, 0);
    for (int c = 0; c < NC; c++) {
        if (c + 1 < NC) {
            issue_chunk((c + 1) * 32, (c + 1) & 1);
            asm volatile("cp.async.wait_group 1;" ::: "memory");
        } else {
            asm volatile("cp.async.wait_group 0;" ::: "memory");
        }
        __syncthreads();
        compute_chunk(c & 1);
        __syncthreads();
    }

    #pragma unroll
    for (int mt = 0; mt < 4; mt++) {
        const int m = m0 + wm * 64 + mt * 16 + g;
        #pragma unroll
        for (int nt = 0; nt < 4; nt++) {
            const int n = n0 + wn * 32 + nt * 8 + t * 2;
            float b0 = bias[n], b1 = bias[n + 1];
            float v00 = acc[mt][nt][0] + b0;
            float v01 = acc[mt][nt][1] + b1;
            float v10 = acc[mt][nt][2] + b0;
            float v11 = acc[mt][nt][3] + b1;
            v00 = (v00 > 0.f) ? v00 : 0.f;
            v01 = (v01 > 0.f) ? v01 : 0.f;
            v10 = (v10 > 0.f) ? v10 : 0.f;
            v11 = (v11 > 0.f) ? v11 : 0.f;
            if (HILO) {
                __nv_bfloat16 h00 = __float2bfloat16(v00);
                __nv_bfloat16 h01 = __float2bfloat16(v01);
                __nv_bfloat16 h10 = __float2bfloat16(v10);
                __nv_bfloat16 h11 = __float2bfloat16(v11);
                __nv_bfloat162 hp0; hp0.x = h00; hp0.y = h01;
                __nv_bfloat162 hp1; hp1.x = h10; hp1.y = h11;
                __nv_bfloat162 lp0;
                lp0.x = __float2bfloat16(v00 - __bfloat162float(h00));
                lp0.y = __float2bfloat16(v01 - __bfloat162float(h01));
                __nv_bfloat162 lp1;
                lp1.x = __float2bfloat16(v10 - __bfloat162float(h10));
                lp1.y = __float2bfloat16(v11 - __bfloat162float(h11));
                *(__nv_bfloat162*)(Ch + (size_t)m * N + n)       = hp0;
                *(__nv_bfloat162*)(Cl + (size_t)m * N + n)       = lp0;
                *(__nv_bfloat162*)(Ch + (size_t)(m + 8) * N + n) = hp1;
                *(__nv_bfloat162*)(Cl + (size_t)(m + 8) * N + n) = lp1;
            } else {
                float2 f0 = make_float2(v00, v01);
                float2 f1 = make_float2(v10, v11);
                *(float2*)(Cf + (size_t)m * N + n)       = f0;
                *(float2*)(Cf + (size_t)(m + 8) * N + n) = f1;
            }
        }
    }
}

// ---------------------------------------------------------------------------
// FC3 split-K GEMM (scalar) + reduce — unchanged
// ---------------------------------------------------------------------------
__global__ __launch_bounds__(256, 2) void fc3_splitk_kernel(
    const float* __restrict__ A,
    const float* __restrict__ Wr)
{
    __shared__ float As[2][8][128];
    __shared__ float Bs[2][8][32];

    const int tid = threadIdx.x;
    const int ks  = blockIdx.x;
    const int m0  = blockIdx.y * 128;
    const int kbeg = ks * (Hh / KSPLIT);
    const int tx = tid & 7;
    const int ty = tid >> 3;

    float acc[4][4];
    #pragma unroll
    for (int i = 0; i < 4; i++)
        #pragma unroll
        for (int j = 0; j < 4; j++) acc[i][j] = 0.f;

    const int r = tid >> 1;
    const int s = (tid & 1) * 4;
    const float* __restrict__ Arow = A + (size_t)(m0 + r) * Hh + kbeg + s;
    const float* __restrict__ Brow = Wr + (size_t)(tid >> 1) * Hh + kbeg + ((tid & 1) * 4);

    float4 a_n; float4 b_n = make_float4(0.f,0.f,0.f,0.f);

    a_n = *(const float4*)&Arow[0];
    if (tid < 64) b_n = *(const float4*)&Brow[0];
    As[0][s + 0][r] = a_n.x; As[0][s + 1][r] = a_n.y;
    As[0][s + 2][r] = a_n.z; As[0][s + 3][r] = a_n.w;
    if (tid < 64) {
        int bn = tid >> 1, bs = (tid & 1) * 4;
        Bs[0][bs + 0][bn] = b_n.x; Bs[0][bs + 1][bn] = b_n.y;
        Bs[0][bs + 2][bn] = b_n.z; Bs[0][bs + 3][bn] = b_n.w;
    }
    __syncthreads();

    int buf = 0;
    const int KC = Hh / KSPLIT;
    for (int k0 = 8; k0 <= KC; k0 += 8) {
        const bool more = (k0 < KC);
        if (more) {
            a_n = *(const float4*)&Arow[k0];
            if (tid < 64) b_n = *(const float4*)&Brow[k0];
        }

        #pragma unroll
        for (int k = 0; k < 8; k++) {
            float4 a0 = *(const float4*)&As[buf][k][ty * 4];
            float4 b0 = *(const float4*)&Bs[buf][k][tx * 4];
            float av[4] = {a0.x, a0.y, a0.z, a0.w};
            float bv[4] = {b0.x, b0.y, b0.z, b0.w};
            #pragma unroll
            for (int ii = 0; ii < 4; ii++)
                #pragma unroll
                for (int jj = 0; jj < 4; jj++)
                    acc[ii][jj] += av[ii] * bv[jj];
        }

        if (more) {
            int nb = buf ^ 1;
            As[nb][s + 0][r] = a_n.x; As[nb][s + 1][r] = a_n.y;
            As[nb][s + 2][r] = a_n.z; As[nb][s + 3][r] = a_n.w;
            if (tid < 64) {
                int bn = tid >> 1, bs = (tid & 1) * 4;
                Bs[nb][bs + 0][bn] = b_n.x; Bs[nb][bs + 1][bn] = b_n.y;
                Bs[nb][bs + 2][bn] = b_n.z; Bs[nb][bs + 3][bn] = b_n.w;
            }
            buf = nb;
            __syncthreads();
        }
    }

    float* __restrict__ part = (float*)g_fc3p + (size_t)ks * Pp * Rr;
    #pragma unroll
    for (int ii = 0; ii < 4; ii++) {
        int m = m0 + ty * 4 + ii;
        #pragma unroll
        for (int jj = 0; jj < 4; jj++) {
            int nn = tx * 4 + jj;
            part[(size_t)m * Rr + nn] = acc[ii][jj];
        }
    }
}

__global__ void fc3_reduce_kernel(const float* __restrict__ br,
                                  float* __restrict__ out)
{
    int i = blockIdx.x * blockDim.x + threadIdx.x;
    if (i < Pp * Rr) {
        const float* p = (const float*)g_fc3p;
        float v = p[i] + p[i + Pp*Rr] + p[i + 2*Pp*Rr] + p[i + 3*Pp*Rr];
        out[i] = v + br[i & (Rr - 1)];
    }
}

// ---------------------------------------------------------------------------
__global__ void pack_kernel(const float* __restrict__ trig,
                            const int* __restrict__ labels,
                            float* __restrict__ out, int out_size)
{
    int i = blockIdx.x * blockDim.x + threadIdx.x;
    const int PR = Pp * Rr;
    const int BT = Bb * Tt;
    if (out_size >= PR + BT && i < BT)        out[PR + i]      = trig[i];
    if (out_size >= PR + BT + Pp && i < Pp)   out[PR + BT + i] = (float)labels[i];
}

// ---------------------------------------------------------------------------
extern "C" void kernel_launch(void* const* d_in, const int* in_sizes, int n_in,
                              void* d_out, int out_size)
{
    const float* x     = (const float*)d_in[0];
    const float* trig  = (const float*)d_in[1];
    const int*   bidx  = (const int*)  d_in[2];
    const int*   hidx  = (const int*)  d_in[3];
    const int*   hspan = (const int*)  d_in[4];
    const int*   tidx  = (const int*)  d_in[5];
    const int*   tspan = (const int*)  d_in[6];
    const int*   labels= (const int*)  d_in[7];
    const float* c1w   = (const float*)d_in[8];
    const float* c1b   = (const float*)d_in[9];
    const float* c2w   = (const float*)d_in[10];
    const float* c2b   = (const float*)d_in[11];
    const float* w1    = (const float*)d_in[12];
    const float* b1    = (const float*)d_in[13];
    const float* w2    = (const float*)d_in[14];
    const float* b2    = (const float*)d_in[15];
    const float* wr    = (const float*)d_in[16];
    const float* br    = (const float*)d_in[17];
    float* out = (float*)d_out;

    __nv_bfloat16 *pxh, *pxl, *px1h, *px1l, *pwt1h, *pwt1l, *pwt2h, *pwt2l;
    __nv_bfloat16 *pmxh, *pmxl, *pw1h, *pw1l, *pw2h, *pw2l, *ph1h, *ph1l;
    float *px1, *pxbte, *ph2;
    cudaGetSymbolAddress((void**)&pxh,   g_xh);
    cudaGetSymbolAddress((void**)&pxl,   g_xl);
    cudaGetSymbolAddress((void**)&px1h,  g_x1h);
    cudaGetSymbolAddress((void**)&px1l,  g_x1l);
    cudaGetSymbolAddress((void**)&pwt1h, g_wt1h);
    cudaGetSymbolAddress((void**)&pwt1l, g_wt1l);
    cudaGetSymbolAddress((void**)&pwt2h, g_wt2h);
    cudaGetSymbolAddress((void**)&pwt2l, g_wt2l);
    cudaGetSymbolAddress((void**)&pmxh,  g_mx_h);
    cudaGetSymbolAddress((void**)&pmxl,  g_mx_l);
    cudaGetSymbolAddress((void**)&pw1h,  g_w1h);
    cudaGetSymbolAddress((void**)&pw1l,  g_w1l);
    cudaGetSymbolAddress((void**)&pw2h,  g_w2h);
    cudaGetSymbolAddress((void**)&pw2l,  g_w2l);
    cudaGetSymbolAddress((void**)&ph1h,  g_h1h);
    cudaGetSymbolAddress((void**)&ph1l,  g_h1l);
    cudaGetSymbolAddress((void**)&px1,   g_x1);
    cudaGetSymbolAddress((void**)&pxbte, g_xbte);
    cudaGetSymbolAddress((void**)&ph2,   g_h2);

    static int smem_set = 0;
    if (!smem_set) {
        cudaFuncSetAttribute(fc_mma_kernel<true>,
                             cudaFuncAttributeMaxDynamicSharedMemorySize, FC_SMEM);
        cudaFuncSetAttribute(fc_mma_kernel<false>,
                             cudaFuncAttributeMaxDynamicSharedMemorySize, FC_SMEM);
        cudaFuncSetAttribute(conv_mma_kernel<0>,
                             cudaFuncAttributeMaxDynamicSharedMemorySize, CONV_SMEM);
        cudaFuncSetAttribute(conv_mma_kernel<1>,
                             cudaFuncAttributeMaxDynamicSharedMemorySize, CONV_SMEM);
        smem_set = 1;
    }

    // Conversions
    cvt_hilo_kernel<<<(Bb*Ee*Tt + 255)/256, 256>>>(x, pxh, pxl, Bb*Ee*Tt);
    cvt_wt_kernel<<<(Ee*Ee*3 + 255)/256, 256>>>(c1w, pwt1h, pwt1l);
    cvt_wt_kernel<<<(Ee*Ee*3 + 255)/256, 256>>>(c2w, pwt2h, pwt2l);
    cvt_hilo_kernel<<<(Hh*Ee + 255)/256, 256>>>(w1, pw1h, pw1l, Hh*Ee);
    cvt_hilo_kernel<<<(Hh*Hh + 255)/256, 256>>>(w2, pw2h, pw2l, Hh*Hh);

    // Conv blocks (tensor cores)
    {
        dim3 grid((Bb * Tt) / 128, Ee / 128);
        conv_mma_kernel<0><<<grid, 256, CONV_SMEM>>>(
            pxh, pxl, pwt1h, pwt1l, c1b, x, px1, px1h, px1l);
        conv_mma_kernel<1><<<grid, 256, CONV_SMEM>>>(
            px1h, px1l, pwt2h, pwt2l, c2b, px1, pxbte, nullptr, nullptr);
    }

    // Span max -> bf16 hi/lo
    span_kernel<<<Pp, 128>>>(bidx, hidx, hspan, tidx, tspan);

    // FC1 (mma bf16x3): (P,512)x(1024,512)^T -> h1 hi/lo, relu
    {
        dim3 grid(Hh / 128, Pp / 128);
        fc_mma_kernel<true><<<grid, 256, FC_SMEM>>>(
            pmxh, pmxl, pw1h, pw1l, b1, Ee, Hh, nullptr, ph1h, ph1l);
    }
    // FC2 (mma bf16x3): (P,1024)x(1024,1024)^T -> h2 fp32, relu
    {
        dim3 grid(Hh / 128, Pp / 128);
        fc_mma_kernel<false><<<grid, 256, FC_SMEM>>>(
            ph1h, ph1l, pw2h, pw2l, b2, Hh, Hh, ph2, nullptr, nullptr);
    }
    // FC3: split-K + reduce into d_out
    {
        dim3 grid(KSPLIT, Pp / 128);
        fc3_splitk_kernel<<<grid, 256>>>(ph2, wr);
        fc3_reduce_kernel<<<(Pp * Rr + 255) / 256, 256>>>(br, out);
    }
    // trig_attn + rel_labels passthrough
    pack_kernel<<<(8192 + 255) / 256, 256>>>(trig, labels, out, out_size);
}